// round 4
// baseline (speedup 1.0000x reference)
#include <cuda_runtime.h>
#include <math.h>

// Problem dims (fixed)
#define B_   2
#define N_Q  5376
#define M_KV 512
#define D_   1536
#define H_   12
#define HD_  128

// Scratch (device globals: allocation-guard safe)
__device__ float g_q[(size_t)B_ * N_Q * D_];          // [B*N, D]   (h*128+hd layout)
__device__ float g_kv[(size_t)B_ * M_KV * 2 * D_];    // [B*M, 2D]  (k | v, each h*128+hd)
__device__ float g_ctx[(size_t)B_ * N_Q * D_];        // [B*N, D]

// ---------------- f32x2 packed-FMA helpers (sm_100a) ----------------
typedef unsigned long long u64;

__device__ __forceinline__ u64 pack2(float lo, float hi) {
    u64 r;
    asm("mov.b64 %0, {%1, %2};" : "=l"(r) : "f"(lo), "f"(hi));
    return r;
}
__device__ __forceinline__ void unpack2(u64 v, float& lo, float& hi) {
    asm("mov.b64 {%0, %1}, %2;" : "=f"(lo), "=f"(hi) : "l"(v));
}
__device__ __forceinline__ void ffma2(u64& d, u64 a, u64 b) {
    asm("fma.rn.f32x2 %0, %1, %2, %0;" : "+l"(d) : "l"(a), "l"(b));
}
__device__ __forceinline__ u64 fmul2(u64 a, u64 b) {
    u64 r;
    asm("mul.rn.f32x2 %0, %1, %2;" : "=l"(r) : "l"(a), "l"(b));
    return r;
}

// ---------------- SGEMM: C[M,N] = A[M,K] @ B[K,N] + bias[N] ----------------
// 128x128 tile, BK=8, 256 threads, 8x8 per thread (as 8 rows x 4 f32x2 col-pairs),
// double-buffered SMEM, f32x2 packed FMA inner product.
__global__ __launch_bounds__(256, 2)
void sgemm_bias(const float* __restrict__ A, const float* __restrict__ B,
                const float* __restrict__ bias, float* __restrict__ C,
                int M, int N, int K)
{
    __shared__ __align__(16) float As[2][8][128];
    __shared__ __align__(16) float Bs[2][8][128];

    const int tid = threadIdx.x;
    const int tx = tid & 15;          // col group
    const int ty = tid >> 4;          // row group
    const int row0 = blockIdx.y * 128;
    const int col0 = blockIdx.x * 128;

    // A-tile load mapping: 128 rows x 8 k, one float4 per thread
    const int ar = tid >> 1;          // 0..127
    const int ac = (tid & 1) * 4;     // 0 or 4
    // B-tile load mapping: 8 k x 128 cols, one float4 per thread
    const int br = tid >> 5;          // 0..7
    const int bc = (tid & 31) * 4;    // 0..124

    const float* Ap = A + (size_t)(row0 + ar) * K + ac;
    const float* Bp = B + (size_t)br * N + col0 + bc;

    u64 acc[8][4];
#pragma unroll
    for (int i = 0; i < 8; i++)
#pragma unroll
        for (int j = 0; j < 4; j++) acc[i][j] = 0ULL;

    // preload tile 0
    float4 av = *(const float4*)Ap;
    float4 bv = *(const float4*)Bp;
    As[0][ac + 0][ar] = av.x; As[0][ac + 1][ar] = av.y;
    As[0][ac + 2][ar] = av.z; As[0][ac + 3][ar] = av.w;
    *(float4*)&Bs[0][br][bc] = bv;
    __syncthreads();

    const int KT = K >> 3;
    int buf = 0;
    for (int kt = 0; kt < KT; kt++) {
        if (kt + 1 < KT) {
            av = *(const float4*)(Ap + (size_t)(kt + 1) * 8);
            bv = *(const float4*)(Bp + (size_t)(kt + 1) * 8 * N);
        }
#pragma unroll
        for (int kk = 0; kk < 8; kk++) {
            float4 a0 = *(const float4*)&As[buf][kk][ty * 4];
            float4 a1 = *(const float4*)&As[buf][kk][ty * 4 + 64];
            float4 b0 = *(const float4*)&Bs[buf][kk][tx * 4];
            float4 b1 = *(const float4*)&Bs[buf][kk][tx * 4 + 64];
            u64 bp[4] = { pack2(b0.x, b0.y), pack2(b0.z, b0.w),
                          pack2(b1.x, b1.y), pack2(b1.z, b1.w) };
            float a[8] = { a0.x, a0.y, a0.z, a0.w, a1.x, a1.y, a1.z, a1.w };
#pragma unroll
            for (int i = 0; i < 8; i++) {
                u64 ai = pack2(a[i], a[i]);
#pragma unroll
                for (int j = 0; j < 4; j++) ffma2(acc[i][j], ai, bp[j]);
            }
        }
        if (kt + 1 < KT) {
            buf ^= 1;
            As[buf][ac + 0][ar] = av.x; As[buf][ac + 1][ar] = av.y;
            As[buf][ac + 2][ar] = av.z; As[buf][ac + 3][ar] = av.w;
            *(float4*)&Bs[buf][br][bc] = bv;
            __syncthreads();
        }
    }

    // epilogue: + bias, vectorized store
    float4 bb0 = *(const float4*)(bias + col0 + tx * 4);
    float4 bb1 = *(const float4*)(bias + col0 + tx * 4 + 64);
    float bvl[8] = { bb0.x, bb0.y, bb0.z, bb0.w, bb1.x, bb1.y, bb1.z, bb1.w };
#pragma unroll
    for (int i = 0; i < 8; i++) {
        int r = row0 + ((i < 4) ? (ty * 4 + i) : (64 + ty * 4 + i - 4));
        float o[8];
#pragma unroll
        for (int j = 0; j < 4; j++) {
            float lo, hi;
            unpack2(acc[i][j], lo, hi);
            o[2 * j] = lo + bvl[2 * j];
            o[2 * j + 1] = hi + bvl[2 * j + 1];
        }
        float4 s0 = { o[0], o[1], o[2], o[3] };
        float4 s1 = { o[4], o[5], o[6], o[7] };
        *(float4*)&C[(size_t)r * N + col0 + tx * 4] = s0;
        *(float4*)&C[(size_t)r * N + col0 + tx * 4 + 64] = s1;
    }
}

// ---------------- RMSNorm over each 128-wide head chunk of q ----------------
__global__ void rmsnorm_kernel(float* __restrict__ q, const float* __restrict__ gscale)
{
    int chunk = blockIdx.x * 8 + (threadIdx.x >> 5);   // (b*N + n)*H + h
    int lane = threadIdx.x & 31;
    float4* base = (float4*)(q + (size_t)chunk * 128);
    float4 v = base[lane];
    float ss = v.x * v.x + v.y * v.y + v.z * v.z + v.w * v.w;
#pragma unroll
    for (int off = 16; off >= 1; off >>= 1)
        ss += __shfl_xor_sync(0xffffffffu, ss, off);
    float r = rsqrtf(ss * (1.0f / 128.0f) + 1e-6f);
    float4 sc = ((const float4*)gscale)[lane];
    v.x *= r * sc.x; v.y *= r * sc.y; v.z *= r * sc.z; v.w *= r * sc.w;
    base[lane] = v;
}

// ---------------- Flash attention: per (b, h, 64-query tile) ----------------
// SMEM: Qt[128][68] (k-major, transposed), Kt[128][68], V[64][128], P[64][64]
#define QT_OFF 0
#define KT_OFF (128 * 68)
#define V_OFF  (2 * 128 * 68)
#define P_OFF  (2 * 128 * 68 + 64 * 128)
#define ATT_SMEM_FLOATS (2 * 128 * 68 + 64 * 128 + 64 * 64)

__global__ __launch_bounds__(256, 1)
void attn_kernel(const float* __restrict__ Q, const float* __restrict__ KV,
                 float* __restrict__ ctx)
{
    extern __shared__ __align__(16) float sm[];
    float* Qs = sm + QT_OFF;
    float* Ks = sm + KT_OFF;
    float* Vs = sm + V_OFF;
    float* Ps = sm + P_OFF;

    const int tid = threadIdx.x;
    const int tx = tid & 15;
    const int ty = tid >> 4;
    const int qt = blockIdx.x, h = blockIdx.y, b = blockIdx.z;
    const float scale = 0.08838834764831845f;  // 1/sqrt(128)

    // Load Q tile (64 rows x 128), store transposed + pre-scaled
    {
        const float* qbase = Q + (size_t)(b * N_Q + qt * 64) * D_ + h * HD_;
#pragma unroll
        for (int it = 0; it < 8; it++) {
            int f = tid + it * 256;
            int r = f >> 5, c4 = (f & 31) * 4;
            float4 v = *(const float4*)(qbase + (size_t)r * D_ + c4);
            Qs[(c4 + 0) * 68 + r] = v.x * scale;
            Qs[(c4 + 1) * 68 + r] = v.y * scale;
            Qs[(c4 + 2) * 68 + r] = v.z * scale;
            Qs[(c4 + 3) * 68 + r] = v.w * scale;
        }
    }

    float m[4], l[4];
    u64 o2[4][4];
#pragma unroll
    for (int i = 0; i < 4; i++) {
        m[i] = -INFINITY; l[i] = 0.f;
#pragma unroll
        for (int j = 0; j < 4; j++) o2[i][j] = 0ULL;
    }

    for (int kt = 0; kt < 8; kt++) {
        __syncthreads();   // prior chunk's reads of Ks/Vs/Ps done; (iter 0: Qs visible via next sync)

        // Load K chunk (transposed) and V chunk (row-major)
        const float* kbase = KV + (size_t)(b * M_KV + kt * 64) * (2 * D_) + h * HD_;
        const float* vbase = kbase + D_;
#pragma unroll
        for (int it = 0; it < 8; it++) {
            int f = tid + it * 256;
            int r = f >> 5, c4 = (f & 31) * 4;
            float4 kv4 = *(const float4*)(kbase + (size_t)r * (2 * D_) + c4);
            Ks[(c4 + 0) * 68 + r] = kv4.x;
            Ks[(c4 + 1) * 68 + r] = kv4.y;
            Ks[(c4 + 2) * 68 + r] = kv4.z;
            Ks[(c4 + 3) * 68 + r] = kv4.w;
            float4 vv = *(const float4*)(vbase + (size_t)r * (2 * D_) + c4);
            *(float4*)&Vs[r * 128 + c4] = vv;
        }
        __syncthreads();

        // S = Qs @ Ks^T : 64x64, per thread 4 rows x 4 cols (2 f32x2 pairs)
        u64 s2[4][2];
#pragma unroll
        for (int i = 0; i < 4; i++) { s2[i][0] = 0ULL; s2[i][1] = 0ULL; }
#pragma unroll 4
        for (int kk = 0; kk < 128; kk++) {
            float4 a = *(const float4*)&Qs[kk * 68 + ty * 4];
            float4 kf = *(const float4*)&Ks[kk * 68 + tx * 4];
            u64 b01 = pack2(kf.x, kf.y);
            u64 b23 = pack2(kf.z, kf.w);
            float av4[4] = { a.x, a.y, a.z, a.w };
#pragma unroll
            for (int i = 0; i < 4; i++) {
                u64 ai = pack2(av4[i], av4[i]);
                ffma2(s2[i][0], ai, b01);
                ffma2(s2[i][1], ai, b23);
            }
        }

        // online softmax update (row owners = 16 threads sharing ty -> shfl over tx)
#pragma unroll
        for (int i = 0; i < 4; i++) {
            float s0, s1, s2v, s3;
            unpack2(s2[i][0], s0, s1);
            unpack2(s2[i][1], s2v, s3);
            float mloc = fmaxf(fmaxf(s0, s1), fmaxf(s2v, s3));
#pragma unroll
            for (int off = 8; off >= 1; off >>= 1)
                mloc = fmaxf(mloc, __shfl_xor_sync(0xffffffffu, mloc, off));
            float mnew = fmaxf(m[i], mloc);
            float corr = __expf(m[i] - mnew);
            float p0 = __expf(s0 - mnew), p1 = __expf(s1 - mnew);
            float p2 = __expf(s2v - mnew), p3 = __expf(s3 - mnew);
            float psum = p0 + p1 + p2 + p3;
#pragma unroll
            for (int off = 8; off >= 1; off >>= 1)
                psum += __shfl_xor_sync(0xffffffffu, psum, off);
            l[i] = l[i] * corr + psum;
            m[i] = mnew;
            float4 pv = { p0, p1, p2, p3 };
            *(float4*)&Ps[(ty * 4 + i) * 64 + tx * 4] = pv;
            u64 c2 = pack2(corr, corr);
#pragma unroll
            for (int j = 0; j < 4; j++) o2[i][j] = fmul2(o2[i][j], c2);
        }
        __syncthreads();

        // O += P @ V : per thread 4 rows x 8 cols (4 f32x2 pairs)
#pragma unroll 2
        for (int j = 0; j < 64; j++) {
            float p0 = Ps[(ty * 4 + 0) * 64 + j];
            float p1 = Ps[(ty * 4 + 1) * 64 + j];
            float p2 = Ps[(ty * 4 + 2) * 64 + j];
            float p3 = Ps[(ty * 4 + 3) * 64 + j];
            float4 v0 = *(const float4*)&Vs[j * 128 + tx * 4];
            float4 v1 = *(const float4*)&Vs[j * 128 + tx * 4 + 64];
            u64 vp[4] = { pack2(v0.x, v0.y), pack2(v0.z, v0.w),
                          pack2(v1.x, v1.y), pack2(v1.z, v1.w) };
            float pv4[4] = { p0, p1, p2, p3 };
#pragma unroll
            for (int i = 0; i < 4; i++) {
                u64 pi = pack2(pv4[i], pv4[i]);
#pragma unroll
                for (int j2 = 0; j2 < 4; j2++) ffma2(o2[i][j2], pi, vp[j2]);
            }
        }
    }

    // normalize + write ctx
#pragma unroll
    for (int i = 0; i < 4; i++) {
        float inv = 1.0f / l[i];
        float o[8];
#pragma unroll
        for (int j = 0; j < 4; j++) {
            float lo, hi;
            unpack2(o2[i][j], lo, hi);
            o[2 * j] = lo * inv;
            o[2 * j + 1] = hi * inv;
        }
        size_t n = (size_t)(b * N_Q + qt * 64 + ty * 4 + i);
        float* cbase = ctx + n * D_ + h * HD_;
        float4 s0 = { o[0], o[1], o[2], o[3] };
        float4 s1 = { o[4], o[5], o[6], o[7] };
        *(float4*)(cbase + tx * 4) = s0;
        *(float4*)(cbase + tx * 4 + 64) = s1;
    }
}

// ---------------- launch ----------------
extern "C" void kernel_launch(void* const* d_in, const int* in_sizes, int n_in,
                              void* d_out, int out_size)
{
    const float* x       = (const float*)d_in[0];
    const float* context = (const float*)d_in[1];
    const float* wq      = (const float*)d_in[2];
    const float* bq      = (const float*)d_in[3];
    const float* wkv     = (const float*)d_in[4];
    const float* bkv     = (const float*)d_in[5];
    const float* wo      = (const float*)d_in[6];
    const float* bo      = (const float*)d_in[7];
    const float* qns     = (const float*)d_in[8];
    float* out = (float*)d_out;

    float *q, *kv, *ctx;
    cudaGetSymbolAddress((void**)&q,   g_q);
    cudaGetSymbolAddress((void**)&kv,  g_kv);
    cudaGetSymbolAddress((void**)&ctx, g_ctx);

    const int att_smem = ATT_SMEM_FLOATS * (int)sizeof(float);  // 118784 B
    cudaFuncSetAttribute(attn_kernel, cudaFuncAttributeMaxDynamicSharedMemorySize, att_smem);

    dim3 blk(256);
    // Q = x @ wq + bq              [10752 x 1536 x 1536]
    sgemm_bias<<<dim3(D_ / 128, (B_ * N_Q) / 128), blk>>>(x, wq, bq, q, B_ * N_Q, D_, D_);
    // per-head RMSNorm on q
    rmsnorm_kernel<<<(B_ * N_Q * H_) / 8, 256>>>(q, qns);
    // KV = context @ wkv + bkv     [1024 x 3072 x 1536]
    sgemm_bias<<<dim3((2 * D_) / 128, (B_ * M_KV) / 128), blk>>>(context, wkv, bkv, kv, B_ * M_KV, 2 * D_, D_);
    // attention
    attn_kernel<<<dim3(N_Q / 64, H_, B_), blk, att_smem>>>(q, kv, ctx);
    // out = ctx @ wo + bo          [10752 x 1536 x 1536]
    sgemm_bias<<<dim3(D_ / 128, (B_ * N_Q) / 128), blk>>>(ctx, wo, bo, out, B_ * N_Q, D_, D_);
}

// round 7
// speedup vs baseline: 1.5901x; 1.5901x over previous
#include <cuda_runtime.h>
#include <cuda_bf16.h>
#include <stdint.h>
#include <math.h>

// Problem dims (fixed)
#define B_   2
#define N_Q  5376
#define M_KV 512
#define D_   1536
#define H_   12
#define HD_  128

// ---------------- scratch (device globals: allocation-guard safe) ----------------
__device__ float g_q[(size_t)B_ * N_Q * D_];          // [B*N, D]
__device__ float g_kv[(size_t)B_ * M_KV * 2 * D_];    // [B*M, 2D]
__device__ float g_ctx[(size_t)B_ * N_Q * D_];        // [B*N, D]

__device__ __nv_bfloat16 g_ahi[(size_t)B_ * N_Q * D_];   // activation hi (x, later ctx)
__device__ __nv_bfloat16 g_alo[(size_t)B_ * N_Q * D_];   // activation lo
__device__ __nv_bfloat16 g_wqhi[(size_t)D_ * D_];
__device__ __nv_bfloat16 g_wqlo[(size_t)D_ * D_];
__device__ __nv_bfloat16 g_wkvhi[(size_t)2 * D_ * D_];
__device__ __nv_bfloat16 g_wkvlo[(size_t)2 * D_ * D_];
__device__ __nv_bfloat16 g_wohi[(size_t)D_ * D_];
__device__ __nv_bfloat16 g_wolo[(size_t)D_ * D_];

// ---------------- helpers ----------------
typedef unsigned long long u64;
typedef unsigned int u32;

__device__ __forceinline__ u32 smem_u32(const void* p) {
    u32 a;
    asm("{ .reg .u64 t; cvta.to.shared.u64 t, %1; cvt.u32.u64 %0, t; }" : "=r"(a) : "l"(p));
    return a;
}
__device__ __forceinline__ u64 pack2(float lo, float hi) {
    u64 r; asm("mov.b64 %0, {%1, %2};" : "=l"(r) : "f"(lo), "f"(hi)); return r;
}
__device__ __forceinline__ void unpack2(u64 v, float& lo, float& hi) {
    asm("mov.b64 {%0, %1}, %2;" : "=f"(lo), "=f"(hi) : "l"(v));
}
__device__ __forceinline__ void ffma2(u64& d, u64 a, u64 b) {
    asm("fma.rn.f32x2 %0, %1, %2, %0;" : "+l"(d) : "l"(a), "l"(b));
}
__device__ __forceinline__ u64 fmul2(u64 a, u64 b) {
    u64 r; asm("mul.rn.f32x2 %0, %1, %2;" : "=l"(r) : "l"(a), "l"(b)); return r;
}

__device__ __forceinline__ void cp_async16(u32 dst, const void* src) {
    asm volatile("cp.async.cg.shared.global [%0], [%1], 16;" :: "r"(dst), "l"(src) : "memory");
}
__device__ __forceinline__ void cp_commit() {
    asm volatile("cp.async.commit_group;" ::: "memory");
}
__device__ __forceinline__ void cp_wait0() {
    asm volatile("cp.async.wait_group 0;" ::: "memory");
}
__device__ __forceinline__ void ldmx4(u32& r0, u32& r1, u32& r2, u32& r3, u32 addr) {
    asm volatile("ldmatrix.sync.aligned.m8n8.x4.shared.b16 {%0,%1,%2,%3}, [%4];"
                 : "=r"(r0), "=r"(r1), "=r"(r2), "=r"(r3) : "r"(addr));
}
__device__ __forceinline__ void ldmx2(u32& r0, u32& r1, u32 addr) {
    asm volatile("ldmatrix.sync.aligned.m8n8.x2.shared.b16 {%0,%1}, [%2];"
                 : "=r"(r0), "=r"(r1) : "r"(addr));
}
__device__ __forceinline__ void mma16816(float* c, const u32* a, const u32* b) {
    asm volatile(
        "mma.sync.aligned.m16n8k16.row.col.f32.bf16.bf16.f32 "
        "{%0,%1,%2,%3}, {%4,%5,%6,%7}, {%8,%9}, {%0,%1,%2,%3};"
        : "+f"(c[0]), "+f"(c[1]), "+f"(c[2]), "+f"(c[3])
        : "r"(a[0]), "r"(a[1]), "r"(a[2]), "r"(a[3]), "r"(b[0]), "r"(b[1]));
}

// ---------------- prep: elementwise fp32 -> (hi, lo) bf16 ----------------
struct alignas(8) B4 { __nv_bfloat16 v[4]; };

__global__ void split_kernel(const float* __restrict__ in, __nv_bfloat16* __restrict__ hi,
                             __nv_bfloat16* __restrict__ lo, int n4)
{
    int i = blockIdx.x * blockDim.x + threadIdx.x;
    if (i >= n4) return;
    float4 v = ((const float4*)in)[i];
    B4 hb, lb;
    float f[4] = { v.x, v.y, v.z, v.w };
#pragma unroll
    for (int j = 0; j < 4; j++) {
        __nv_bfloat16 h = __float2bfloat16(f[j]);
        hb.v[j] = h;
        lb.v[j] = __float2bfloat16(f[j] - __bfloat162float(h));
    }
    ((B4*)hi)[i] = hb;
    ((B4*)lo)[i] = lb;
}

// ---------------- prep: transpose + split, fp32 [K,N] -> bf16 [N,K] hi/lo ----------------
__global__ void tsplit_kernel(const float* __restrict__ in, __nv_bfloat16* __restrict__ hi,
                              __nv_bfloat16* __restrict__ lo, int K, int N)
{
    __shared__ float t[32][33];
    int n0 = blockIdx.x * 32, k0 = blockIdx.y * 32;
    int tx = threadIdx.x, ty = threadIdx.y;      // 32 x 8
#pragma unroll
    for (int j = 0; j < 4; j++)
        t[ty + 8 * j][tx] = in[(size_t)(k0 + ty + 8 * j) * N + n0 + tx];
    __syncthreads();
#pragma unroll
    for (int j = 0; j < 4; j++) {
        int r = ty + 8 * j;                      // local n index
        float v = t[tx][r];                      // = in[k0+tx][n0+r]
        __nv_bfloat16 h = __float2bfloat16(v);
        size_t o = (size_t)(n0 + r) * K + k0 + tx;
        hi[o] = h;
        lo[o] = __float2bfloat16(v - __bfloat162float(h));
    }
}

// ---------------- split-bf16 GEMM via mma.sync (HMMA) ----------------
// C[M,N] = (Ahi+Alo)[M,K] @ (Bhi+Blo)^T + bias      (B stored [N,K] K-major)
// CTA 128x128x32, 8 warps (2x4), warp tile 64x32, double-buffered cp.async stages.
// SMEM stage: Ahi|Alo|Bhi|Blo, each 128 rows x 32 bf16, padded row stride 40 bf16 (80B).
#define GROW_B   80                          // padded row stride bytes
#define GTILE_B  (128 * GROW_B)              // 10240 B
#define GSTAGE_B (4 * GTILE_B)               // 40960 B
#define GEMM_SMEM (2 * GSTAGE_B)             // 81920 B

__global__ __launch_bounds__(256, 2)
void gemm_mma(const __nv_bfloat16* __restrict__ Ahi, const __nv_bfloat16* __restrict__ Alo,
              const __nv_bfloat16* __restrict__ Bhi, const __nv_bfloat16* __restrict__ Blo,
              const float* __restrict__ bias, float* __restrict__ C,
              int M, int N, int K)
{
    extern __shared__ __align__(16) char sm[];
    const u32 sbase = smem_u32(sm);
    const int tid = threadIdx.x;
    const int wid = tid >> 5, lane = tid & 31;
    const int wm = wid >> 2;                 // 0..1 : warp row
    const int wn = wid & 3;                  // 0..3 : warp col
    const int row0 = blockIdx.y * 128, col0 = blockIdx.x * 128;

    const int ku4 = K >> 3;                  // uint4 per bf16 row
    const uint4* srcs[4] = {
        (const uint4*)Ahi + (size_t)row0 * ku4,
        (const uint4*)Alo + (size_t)row0 * ku4,
        (const uint4*)Bhi + (size_t)col0 * ku4,
        (const uint4*)Blo + (size_t)col0 * ku4 };

    // per-thread load mapping: 512 uint4 per array per chunk; 2 per array per thread
    const int lr0 = tid >> 2;                // row for j=0 (0..63)
    const int lc = tid & 3;                  // uint4 col within 32-bf16 chunk

    auto load_chunk = [&](int c, int s) {
        const u32 stb = sbase + s * GSTAGE_B;
#pragma unroll
        for (int t = 0; t < 4; t++) {
            const uint4* gp = srcs[t] + (size_t)c * 4 + lc;
#pragma unroll
            for (int j = 0; j < 2; j++) {
                int r = lr0 + j * 64;
                cp_async16(stb + t * GTILE_B + r * GROW_B + lc * 16,
                           gp + (size_t)r * ku4);
            }
        }
        cp_commit();
    };

    float acc[4][4][4];
#pragma unroll
    for (int i = 0; i < 4; i++)
#pragma unroll
        for (int j = 0; j < 4; j++)
#pragma unroll
            for (int e = 0; e < 4; e++) acc[i][j][e] = 0.f;

    load_chunk(0, 0);
    cp_wait0();
    __syncthreads();

    const int NC = K >> 5;                   // 48 chunks of 32
    for (int c = 0; c < NC; c++) {
        const int s = c & 1;
        if (c + 1 < NC) load_chunk(c + 1, s ^ 1);

        const u32 abase = sbase + s * GSTAGE_B;
        const u32 bbase = abase + 2 * GTILE_B;
#pragma unroll
        for (int ks = 0; ks < 2; ks++) {
            u32 ahi[4][4], alo[4][4];
            const u32 acol2 = (ks * 16 + ((lane >> 4) << 3)) * 2;
#pragma unroll
            for (int mt = 0; mt < 4; mt++) {
                u32 ad = abase + (u32)((wm * 64 + mt * 16 + (lane & 15)) * GROW_B) + acol2;
                ldmx4(ahi[mt][0], ahi[mt][1], ahi[mt][2], ahi[mt][3], ad);
                ldmx4(alo[mt][0], alo[mt][1], alo[mt][2], alo[mt][3], ad + GTILE_B);
            }
            const u32 bcol2 = (ks * 16 + (((lane >> 3) & 1) << 3)) * 2;
#pragma unroll
            for (int nt = 0; nt < 4; nt++) {
                u32 bh[2], bl[2];
                u32 bd = bbase + (u32)((wn * 32 + nt * 8 + (lane & 7)) * GROW_B) + bcol2;
                ldmx2(bh[0], bh[1], bd);
                ldmx2(bl[0], bl[1], bd + GTILE_B);
#pragma unroll
                for (int mt = 0; mt < 4; mt++) {
                    mma16816(acc[mt][nt], ahi[mt], bh);
                    mma16816(acc[mt][nt], ahi[mt], bl);
                    mma16816(acc[mt][nt], alo[mt], bh);
                }
            }
        }
        cp_wait0();
        __syncthreads();
    }

    // epilogue: + bias, float2 stores
    const int lr = lane >> 2;                // 0..7
    const int ln = (lane & 3) * 2;           // 0,2,4,6
#pragma unroll
    for (int mt = 0; mt < 4; mt++) {
#pragma unroll
        for (int nt = 0; nt < 4; nt++) {
            int col = col0 + wn * 32 + nt * 8 + ln;
            float2 bv = *(const float2*)(bias + col);
            int r0 = row0 + wm * 64 + mt * 16 + lr;
            float2 v0 = { acc[mt][nt][0] + bv.x, acc[mt][nt][1] + bv.y };
            float2 v1 = { acc[mt][nt][2] + bv.x, acc[mt][nt][3] + bv.y };
            *(float2*)(C + (size_t)r0 * N + col) = v0;
            *(float2*)(C + (size_t)(r0 + 8) * N + col) = v1;
        }
    }
}

// ---------------- RMSNorm over each 128-wide head chunk of q ----------------
__global__ void rmsnorm_kernel(float* __restrict__ q, const float* __restrict__ gscale)
{
    int chunk = blockIdx.x * 8 + (threadIdx.x >> 5);
    int lane = threadIdx.x & 31;
    float4* base = (float4*)(q + (size_t)chunk * 128);
    float4 v = base[lane];
    float ss = v.x * v.x + v.y * v.y + v.z * v.z + v.w * v.w;
#pragma unroll
    for (int off = 16; off >= 1; off >>= 1)
        ss += __shfl_xor_sync(0xffffffffu, ss, off);
    float r = rsqrtf(ss * (1.0f / 128.0f) + 1e-6f);
    float4 sc = ((const float4*)gscale)[lane];
    v.x *= r * sc.x; v.y *= r * sc.y; v.z *= r * sc.z; v.w *= r * sc.w;
    base[lane] = v;
}

// ---------------- Flash attention (fp32 f32x2), per (b, h, 64-query tile) ----------------
#define QT_OFF 0
#define KT_OFF (128 * 68)
#define V_OFF  (2 * 128 * 68)
#define P_OFF  (2 * 128 * 68 + 64 * 128)
#define ATT_SMEM_FLOATS (2 * 128 * 68 + 64 * 128 + 64 * 64)

__global__ __launch_bounds__(256, 1)
void attn_kernel(const float* __restrict__ Q, const float* __restrict__ KV,
                 float* __restrict__ ctx)
{
    extern __shared__ __align__(16) float smf[];
    float* Qs = smf + QT_OFF;
    float* Ks = smf + KT_OFF;
    float* Vs = smf + V_OFF;
    float* Ps = smf + P_OFF;

    const int tid = threadIdx.x;
    const int tx = tid & 15;
    const int ty = tid >> 4;
    const int qt = blockIdx.x, h = blockIdx.y, b = blockIdx.z;
    const float scale = 0.08838834764831845f;

    {
        const float* qbase = Q + (size_t)(b * N_Q + qt * 64) * D_ + h * HD_;
#pragma unroll
        for (int it = 0; it < 8; it++) {
            int f = tid + it * 256;
            int r = f >> 5, c4 = (f & 31) * 4;
            float4 v = *(const float4*)(qbase + (size_t)r * D_ + c4);
            Qs[(c4 + 0) * 68 + r] = v.x * scale;
            Qs[(c4 + 1) * 68 + r] = v.y * scale;
            Qs[(c4 + 2) * 68 + r] = v.z * scale;
            Qs[(c4 + 3) * 68 + r] = v.w * scale;
        }
    }

    float m[4], l[4];
    u64 o2[4][4];
#pragma unroll
    for (int i = 0; i < 4; i++) {
        m[i] = -INFINITY; l[i] = 0.f;
#pragma unroll
        for (int j = 0; j < 4; j++) o2[i][j] = 0ULL;
    }

    for (int kt = 0; kt < 8; kt++) {
        __syncthreads();

        const float* kbase = KV + (size_t)(b * M_KV + kt * 64) * (2 * D_) + h * HD_;
        const float* vbase = kbase + D_;
#pragma unroll
        for (int it = 0; it < 8; it++) {
            int f = tid + it * 256;
            int r = f >> 5, c4 = (f & 31) * 4;
            float4 kv4 = *(const float4*)(kbase + (size_t)r * (2 * D_) + c4);
            Ks[(c4 + 0) * 68 + r] = kv4.x;
            Ks[(c4 + 1) * 68 + r] = kv4.y;
            Ks[(c4 + 2) * 68 + r] = kv4.z;
            Ks[(c4 + 3) * 68 + r] = kv4.w;
            float4 vv = *(const float4*)(vbase + (size_t)r * (2 * D_) + c4);
            *(float4*)&Vs[r * 128 + c4] = vv;
        }
        __syncthreads();

        u64 s2[4][2];
#pragma unroll
        for (int i = 0; i < 4; i++) { s2[i][0] = 0ULL; s2[i][1] = 0ULL; }
#pragma unroll 4
        for (int kk = 0; kk < 128; kk++) {
            float4 a = *(const float4*)&Qs[kk * 68 + ty * 4];
            float4 kf = *(const float4*)&Ks[kk * 68 + tx * 4];
            u64 b01 = pack2(kf.x, kf.y);
            u64 b23 = pack2(kf.z, kf.w);
            float av4[4] = { a.x, a.y, a.z, a.w };
#pragma unroll
            for (int i = 0; i < 4; i++) {
                u64 ai = pack2(av4[i], av4[i]);
                ffma2(s2[i][0], ai, b01);
                ffma2(s2[i][1], ai, b23);
            }
        }

#pragma unroll
        for (int i = 0; i < 4; i++) {
            float s0, s1, s2v, s3;
            unpack2(s2[i][0], s0, s1);
            unpack2(s2[i][1], s2v, s3);
            float mloc = fmaxf(fmaxf(s0, s1), fmaxf(s2v, s3));
#pragma unroll
            for (int off = 8; off >= 1; off >>= 1)
                mloc = fmaxf(mloc, __shfl_xor_sync(0xffffffffu, mloc, off));
            float mnew = fmaxf(m[i], mloc);
            float corr = __expf(m[i] - mnew);
            float p0 = __expf(s0 - mnew), p1 = __expf(s1 - mnew);
            float p2 = __expf(s2v - mnew), p3 = __expf(s3 - mnew);
            float psum = p0 + p1 + p2 + p3;
#pragma unroll
            for (int off = 8; off >= 1; off >>= 1)
                psum += __shfl_xor_sync(0xffffffffu, psum, off);
            l[i] = l[i] * corr + psum;
            m[i] = mnew;
            float4 pv = { p0, p1, p2, p3 };
            *(float4*)&Ps[(ty * 4 + i) * 64 + tx * 4] = pv;
            u64 c2 = pack2(corr, corr);
#pragma unroll
            for (int j = 0; j < 4; j++) o2[i][j] = fmul2(o2[i][j], c2);
        }
        __syncthreads();

#pragma unroll 2
        for (int j = 0; j < 64; j++) {
            float p0 = Ps[(ty * 4 + 0) * 64 + j];
            float p1 = Ps[(ty * 4 + 1) * 64 + j];
            float p2 = Ps[(ty * 4 + 2) * 64 + j];
            float p3 = Ps[(ty * 4 + 3) * 64 + j];
            float4 v0 = *(const float4*)&Vs[j * 128 + tx * 4];
            float4 v1 = *(const float4*)&Vs[j * 128 + tx * 4 + 64];
            u64 vp[4] = { pack2(v0.x, v0.y), pack2(v0.z, v0.w),
                          pack2(v1.x, v1.y), pack2(v1.z, v1.w) };
            float pv4[4] = { p0, p1, p2, p3 };
#pragma unroll
            for (int i = 0; i < 4; i++) {
                u64 pi = pack2(pv4[i], pv4[i]);
#pragma unroll
                for (int j2 = 0; j2 < 4; j2++) ffma2(o2[i][j2], pi, vp[j2]);
            }
        }
    }

#pragma unroll
    for (int i = 0; i < 4; i++) {
        float inv = 1.0f / l[i];
        float o[8];
#pragma unroll
        for (int j = 0; j < 4; j++) {
            float lo, hi;
            unpack2(o2[i][j], lo, hi);
            o[2 * j] = lo * inv;
            o[2 * j + 1] = hi * inv;
        }
        size_t n = (size_t)(b * N_Q + qt * 64 + ty * 4 + i);
        float* cbase = ctx + n * D_ + h * HD_;
        float4 s0 = { o[0], o[1], o[2], o[3] };
        float4 s1 = { o[4], o[5], o[6], o[7] };
        *(float4*)(cbase + tx * 4) = s0;
        *(float4*)(cbase + tx * 4 + 64) = s1;
    }
}

// ---------------- launch ----------------
extern "C" void kernel_launch(void* const* d_in, const int* in_sizes, int n_in,
                              void* d_out, int out_size)
{
    const float* x       = (const float*)d_in[0];
    const float* context = (const float*)d_in[1];
    const float* wq      = (const float*)d_in[2];
    const float* bq      = (const float*)d_in[3];
    const float* wkv     = (const float*)d_in[4];
    const float* bkv     = (const float*)d_in[5];
    const float* wo      = (const float*)d_in[6];
    const float* bo      = (const float*)d_in[7];
    const float* qns     = (const float*)d_in[8];
    float* out = (float*)d_out;

    float *q, *kv, *ctx;
    __nv_bfloat16 *ahi, *alo, *wqhi, *wqlo, *wkvhi, *wkvlo, *wohi, *wolo;
    cudaGetSymbolAddress((void**)&q,    g_q);
    cudaGetSymbolAddress((void**)&kv,   g_kv);
    cudaGetSymbolAddress((void**)&ctx,  g_ctx);
    cudaGetSymbolAddress((void**)&ahi,  g_ahi);
    cudaGetSymbolAddress((void**)&alo,  g_alo);
    cudaGetSymbolAddress((void**)&wqhi, g_wqhi);
    cudaGetSymbolAddress((void**)&wqlo, g_wqlo);
    cudaGetSymbolAddress((void**)&wkvhi, g_wkvhi);
    cudaGetSymbolAddress((void**)&wkvlo, g_wkvlo);
    cudaGetSymbolAddress((void**)&wohi, g_wohi);
    cudaGetSymbolAddress((void**)&wolo, g_wolo);

    const int att_smem = ATT_SMEM_FLOATS * (int)sizeof(float);
    cudaFuncSetAttribute(attn_kernel, cudaFuncAttributeMaxDynamicSharedMemorySize, att_smem);
    cudaFuncSetAttribute(gemm_mma, cudaFuncAttributeMaxDynamicSharedMemorySize, GEMM_SMEM);

    // weight transpose+split: [K,N] fp32 -> [N,K] bf16 hi/lo
    tsplit_kernel<<<dim3(D_ / 32, D_ / 32), dim3(32, 8)>>>(wq, wqhi, wqlo, D_, D_);
    tsplit_kernel<<<dim3((2 * D_) / 32, D_ / 32), dim3(32, 8)>>>(wkv, wkvhi, wkvlo, D_, 2 * D_);
    tsplit_kernel<<<dim3(D_ / 32, D_ / 32), dim3(32, 8)>>>(wo, wohi, wolo, D_, D_);

    // Q = x @ wq + bq
    {
        int n4 = (B_ * N_Q * D_) / 4;
        split_kernel<<<(n4 + 255) / 256, 256>>>(x, ahi, alo, n4);
        gemm_mma<<<dim3(D_ / 128, (B_ * N_Q) / 128), 256, GEMM_SMEM>>>(
            ahi, alo, wqhi, wqlo, bq, q, B_ * N_Q, D_, D_);
    }
    rmsnorm_kernel<<<(B_ * N_Q * H_) / 8, 256>>>(q, qns);

    // KV = context @ wkv + bkv
    {
        int n4 = (B_ * M_KV * D_) / 4;
        split_kernel<<<(n4 + 255) / 256, 256>>>(context, ahi, alo, n4);
        gemm_mma<<<dim3((2 * D_) / 128, (B_ * M_KV) / 128), 256, GEMM_SMEM>>>(
            ahi, alo, wkvhi, wkvlo, bkv, kv, B_ * M_KV, 2 * D_, D_);
    }

    // attention
    attn_kernel<<<dim3(N_Q / 64, H_, B_), 256, att_smem>>>(q, kv, ctx);

    // out = ctx @ wo + bo
    {
        int n4 = (B_ * N_Q * D_) / 4;
        split_kernel<<<(n4 + 255) / 256, 256>>>(ctx, ahi, alo, n4);
        gemm_mma<<<dim3(D_ / 128, (B_ * N_Q) / 128), 256, GEMM_SMEM>>>(
            ahi, alo, wohi, wolo, bo, out, B_ * N_Q, D_, D_);
    }
}

// round 8
// speedup vs baseline: 2.6810x; 1.6861x over previous
#include <cuda_runtime.h>
#include <cuda_bf16.h>
#include <stdint.h>
#include <math.h>

// Problem dims (fixed)
#define B_   2
#define N_Q  5376
#define M_KV 512
#define D_   1536
#define H_   12
#define HD_  128

// ---------------- scratch (device globals: allocation-guard safe) ----------------
__device__ float g_q[(size_t)B_ * N_Q * D_];          // [B*N, D] fp32 Q from gemm
__device__ float g_kv[(size_t)B_ * M_KV * 2 * D_];    // [B*M, 2D] fp32 KV from gemm

__device__ __nv_bfloat16 g_ahi[(size_t)B_ * N_Q * D_];   // activation hi (x, ctx)
__device__ __nv_bfloat16 g_alo[(size_t)B_ * N_Q * D_];   // activation lo
__device__ __nv_bfloat16 g_qhi[(size_t)B_ * N_Q * D_];
__device__ __nv_bfloat16 g_qlo[(size_t)B_ * N_Q * D_];
__device__ __nv_bfloat16 g_kvhi[(size_t)B_ * M_KV * 2 * D_];
__device__ __nv_bfloat16 g_kvlo[(size_t)B_ * M_KV * 2 * D_];
__device__ __nv_bfloat16 g_wqhi[(size_t)D_ * D_];
__device__ __nv_bfloat16 g_wqlo[(size_t)D_ * D_];
__device__ __nv_bfloat16 g_wkvhi[(size_t)2 * D_ * D_];
__device__ __nv_bfloat16 g_wkvlo[(size_t)2 * D_ * D_];
__device__ __nv_bfloat16 g_wohi[(size_t)D_ * D_];
__device__ __nv_bfloat16 g_wolo[(size_t)D_ * D_];

// ---------------- helpers ----------------
typedef unsigned long long u64;
typedef unsigned int u32;

__device__ __forceinline__ u32 smem_u32(const void* p) {
    u32 a;
    asm("{ .reg .u64 t; cvta.to.shared.u64 t, %1; cvt.u32.u64 %0, t; }" : "=r"(a) : "l"(p));
    return a;
}
__device__ __forceinline__ void cp_async16(u32 dst, const void* src) {
    asm volatile("cp.async.cg.shared.global [%0], [%1], 16;" :: "r"(dst), "l"(src) : "memory");
}
__device__ __forceinline__ void cp_commit() {
    asm volatile("cp.async.commit_group;" ::: "memory");
}
__device__ __forceinline__ void cp_wait0() {
    asm volatile("cp.async.wait_group 0;" ::: "memory");
}
__device__ __forceinline__ void ldmx4(u32& r0, u32& r1, u32& r2, u32& r3, u32 addr) {
    asm volatile("ldmatrix.sync.aligned.m8n8.x4.shared.b16 {%0,%1,%2,%3}, [%4];"
                 : "=r"(r0), "=r"(r1), "=r"(r2), "=r"(r3) : "r"(addr));
}
__device__ __forceinline__ void ldmx4t(u32& r0, u32& r1, u32& r2, u32& r3, u32 addr) {
    asm volatile("ldmatrix.sync.aligned.m8n8.x4.trans.shared.b16 {%0,%1,%2,%3}, [%4];"
                 : "=r"(r0), "=r"(r1), "=r"(r2), "=r"(r3) : "r"(addr));
}
__device__ __forceinline__ void ldmx2(u32& r0, u32& r1, u32 addr) {
    asm volatile("ldmatrix.sync.aligned.m8n8.x2.shared.b16 {%0,%1}, [%2];"
                 : "=r"(r0), "=r"(r1) : "r"(addr));
}
__device__ __forceinline__ void mma16816(float* c, const u32* a, const u32* b) {
    asm volatile(
        "mma.sync.aligned.m16n8k16.row.col.f32.bf16.bf16.f32 "
        "{%0,%1,%2,%3}, {%4,%5,%6,%7}, {%8,%9}, {%0,%1,%2,%3};"
        : "+f"(c[0]), "+f"(c[1]), "+f"(c[2]), "+f"(c[3])
        : "r"(a[0]), "r"(a[1]), "r"(a[2]), "r"(a[3]), "r"(b[0]), "r"(b[1]));
}
// pack two f32 into bf16x2: result.lo = cvt(lo), result.hi = cvt(hi)
__device__ __forceinline__ u32 bf16x2_pack(float hi, float lo) {
    u32 r; asm("cvt.rn.bf16x2.f32 %0, %1, %2;" : "=r"(r) : "f"(hi), "f"(lo)); return r;
}
// split packed pair into residuals (exact: bf16->f32 is bit-shift)
__device__ __forceinline__ u32 bf16x2_residual(u32 hi_packed, float p0, float p1) {
    float f0 = __uint_as_float(hi_packed << 16);
    float f1 = __uint_as_float(hi_packed & 0xFFFF0000u);
    return bf16x2_pack(p1 - f1, p0 - f0);
}

// ---------------- prep: elementwise fp32 -> (hi, lo) bf16 ----------------
struct alignas(8) B4 { __nv_bfloat16 v[4]; };

__global__ void split_kernel(const float* __restrict__ in, __nv_bfloat16* __restrict__ hi,
                             __nv_bfloat16* __restrict__ lo, int n4)
{
    int i = blockIdx.x * blockDim.x + threadIdx.x;
    if (i >= n4) return;
    float4 v = ((const float4*)in)[i];
    B4 hb, lb;
    float f[4] = { v.x, v.y, v.z, v.w };
#pragma unroll
    for (int j = 0; j < 4; j++) {
        __nv_bfloat16 h = __float2bfloat16(f[j]);
        hb.v[j] = h;
        lb.v[j] = __float2bfloat16(f[j] - __bfloat162float(h));
    }
    ((B4*)hi)[i] = hb;
    ((B4*)lo)[i] = lb;
}

// ---------------- prep: transpose + split, fp32 [K,N] -> bf16 [N,K] hi/lo ----------------
__global__ void tsplit_kernel(const float* __restrict__ in, __nv_bfloat16* __restrict__ hi,
                              __nv_bfloat16* __restrict__ lo, int K, int N)
{
    __shared__ float t[32][33];
    int n0 = blockIdx.x * 32, k0 = blockIdx.y * 32;
    int tx = threadIdx.x, ty = threadIdx.y;      // 32 x 8
#pragma unroll
    for (int j = 0; j < 4; j++)
        t[ty + 8 * j][tx] = in[(size_t)(k0 + ty + 8 * j) * N + n0 + tx];
    __syncthreads();
#pragma unroll
    for (int j = 0; j < 4; j++) {
        int r = ty + 8 * j;
        float v = t[tx][r];
        __nv_bfloat16 h = __float2bfloat16(v);
        size_t o = (size_t)(n0 + r) * K + k0 + tx;
        hi[o] = h;
        lo[o] = __float2bfloat16(v - __bfloat162float(h));
    }
}

// ---------------- split-bf16 GEMM via mma.sync (HMMA) ----------------
#define GROW_B   80
#define GTILE_B  (128 * GROW_B)
#define GSTAGE_B (4 * GTILE_B)
#define GEMM_SMEM (2 * GSTAGE_B)

__global__ __launch_bounds__(256, 2)
void gemm_mma(const __nv_bfloat16* __restrict__ Ahi, const __nv_bfloat16* __restrict__ Alo,
              const __nv_bfloat16* __restrict__ Bhi, const __nv_bfloat16* __restrict__ Blo,
              const float* __restrict__ bias, float* __restrict__ C,
              int M, int N, int K)
{
    extern __shared__ __align__(16) char sm[];
    const u32 sbase = smem_u32(sm);
    const int tid = threadIdx.x;
    const int wid = tid >> 5, lane = tid & 31;
    const int wm = wid >> 2;
    const int wn = wid & 3;
    const int row0 = blockIdx.y * 128, col0 = blockIdx.x * 128;

    const int ku4 = K >> 3;
    const uint4* srcs[4] = {
        (const uint4*)Ahi + (size_t)row0 * ku4,
        (const uint4*)Alo + (size_t)row0 * ku4,
        (const uint4*)Bhi + (size_t)col0 * ku4,
        (const uint4*)Blo + (size_t)col0 * ku4 };

    const int lr0 = tid >> 2;
    const int lc = tid & 3;

    auto load_chunk = [&](int c, int s) {
        const u32 stb = sbase + s * GSTAGE_B;
#pragma unroll
        for (int t = 0; t < 4; t++) {
            const uint4* gp = srcs[t] + (size_t)c * 4 + lc;
#pragma unroll
            for (int j = 0; j < 2; j++) {
                int r = lr0 + j * 64;
                cp_async16(stb + t * GTILE_B + r * GROW_B + lc * 16,
                           gp + (size_t)r * ku4);
            }
        }
        cp_commit();
    };

    float acc[4][4][4];
#pragma unroll
    for (int i = 0; i < 4; i++)
#pragma unroll
        for (int j = 0; j < 4; j++)
#pragma unroll
            for (int e = 0; e < 4; e++) acc[i][j][e] = 0.f;

    load_chunk(0, 0);
    cp_wait0();
    __syncthreads();

    const int NC = K >> 5;
    for (int c = 0; c < NC; c++) {
        const int s = c & 1;
        if (c + 1 < NC) load_chunk(c + 1, s ^ 1);

        const u32 abase = sbase + s * GSTAGE_B;
        const u32 bbase = abase + 2 * GTILE_B;
#pragma unroll
        for (int ks = 0; ks < 2; ks++) {
            u32 ahi[4][4], alo[4][4];
            const u32 acol2 = (ks * 16 + ((lane >> 4) << 3)) * 2;
#pragma unroll
            for (int mt = 0; mt < 4; mt++) {
                u32 ad = abase + (u32)((wm * 64 + mt * 16 + (lane & 15)) * GROW_B) + acol2;
                ldmx4(ahi[mt][0], ahi[mt][1], ahi[mt][2], ahi[mt][3], ad);
                ldmx4(alo[mt][0], alo[mt][1], alo[mt][2], alo[mt][3], ad + GTILE_B);
            }
            const u32 bcol2 = (ks * 16 + (((lane >> 3) & 1) << 3)) * 2;
#pragma unroll
            for (int nt = 0; nt < 4; nt++) {
                u32 bh[2], bl[2];
                u32 bd = bbase + (u32)((wn * 32 + nt * 8 + (lane & 7)) * GROW_B) + bcol2;
                ldmx2(bh[0], bh[1], bd);
                ldmx2(bl[0], bl[1], bd + GTILE_B);
#pragma unroll
                for (int mt = 0; mt < 4; mt++) {
                    mma16816(acc[mt][nt], ahi[mt], bh);
                    mma16816(acc[mt][nt], ahi[mt], bl);
                    mma16816(acc[mt][nt], alo[mt], bh);
                }
            }
        }
        cp_wait0();
        __syncthreads();
    }

    const int lr = lane >> 2;
    const int ln = (lane & 3) * 2;
#pragma unroll
    for (int mt = 0; mt < 4; mt++) {
#pragma unroll
        for (int nt = 0; nt < 4; nt++) {
            int col = col0 + wn * 32 + nt * 8 + ln;
            float2 bv = *(const float2*)(bias + col);
            int r0 = row0 + wm * 64 + mt * 16 + lr;
            float2 v0 = { acc[mt][nt][0] + bv.x, acc[mt][nt][1] + bv.y };
            float2 v1 = { acc[mt][nt][2] + bv.x, acc[mt][nt][3] + bv.y };
            *(float2*)(C + (size_t)r0 * N + col) = v0;
            *(float2*)(C + (size_t)(r0 + 8) * N + col) = v1;
        }
    }
}

// ---------------- RMSNorm + scale + split: q fp32 -> qhi/qlo bf16 ----------------
__global__ void rmsnorm_split_kernel(const float* __restrict__ q, const float* __restrict__ gscale,
                                     __nv_bfloat16* __restrict__ qhi, __nv_bfloat16* __restrict__ qlo)
{
    int chunk = blockIdx.x * 8 + (threadIdx.x >> 5);   // (b*N + n)*H + h
    int lane = threadIdx.x & 31;
    const float4* base = (const float4*)(q + (size_t)chunk * 128);
    float4 v = base[lane];
    float ss = v.x * v.x + v.y * v.y + v.z * v.z + v.w * v.w;
#pragma unroll
    for (int off = 16; off >= 1; off >>= 1)
        ss += __shfl_xor_sync(0xffffffffu, ss, off);
    float r = rsqrtf(ss * (1.0f / 128.0f) + 1e-6f) * 0.08838834764831845f; // * 1/sqrt(HD)
    float4 sc = ((const float4*)gscale)[lane];
    float f[4] = { v.x * r * sc.x, v.y * r * sc.y, v.z * r * sc.z, v.w * r * sc.w };
    B4 hb, lb;
#pragma unroll
    for (int j = 0; j < 4; j++) {
        __nv_bfloat16 h = __float2bfloat16(f[j]);
        hb.v[j] = h;
        lb.v[j] = __float2bfloat16(f[j] - __bfloat162float(h));
    }
    ((B4*)qhi)[(size_t)chunk * 32 + lane] = hb;
    ((B4*)qlo)[(size_t)chunk * 32 + lane] = lb;
}

// ---------------- Flash attention via mma.sync, split-bf16 both GEMMs ----------------
// CTA: (128-query tile, h, b). 8 warps x 16 rows. 8 key-chunks of 64, double-buffered.
#define SROW_E 136
#define SROW_B 272
#define AQ_TILE (128 * SROW_B)      // 34816
#define AKV_TILE (64 * SROW_B)      // 17408
#define AQ_TOT (2 * AQ_TILE)        // 69632
#define AKV_STAGE (4 * AKV_TILE)    // 69632: Khi|Klo|Vhi|Vlo
#define ATT_SMEM (AQ_TOT + 2 * AKV_STAGE)  // 208896

__global__ __launch_bounds__(256, 1)
void attn_mma(const __nv_bfloat16* __restrict__ qhi, const __nv_bfloat16* __restrict__ qlo,
              const __nv_bfloat16* __restrict__ kvhi, const __nv_bfloat16* __restrict__ kvlo,
              __nv_bfloat16* __restrict__ chi, __nv_bfloat16* __restrict__ clo)
{
    extern __shared__ __align__(16) char sm[];
    const u32 sb = smem_u32(sm);
    const int tid = threadIdx.x, wid = tid >> 5, lane = tid & 31;
    const int q0 = blockIdx.x * 128, h = blockIdx.y, b = blockIdx.z;

    // ---- Q tiles (hi, lo) load: 128 rows x 128 bf16 each ----
    {
        const __nv_bfloat16* s0 = qhi + (size_t)(b * N_Q + q0) * D_ + h * HD_;
        const __nv_bfloat16* s1 = qlo + (size_t)(b * N_Q + q0) * D_ + h * HD_;
#pragma unroll
        for (int j = 0; j < 8; j++) {
            int idx = tid + j * 256;
            int r = idx >> 4, c = idx & 15;
            cp_async16(sb + r * SROW_B + c * 16, s0 + (size_t)r * D_ + c * 8);
            cp_async16(sb + AQ_TILE + r * SROW_B + c * 16, s1 + (size_t)r * D_ + c * 8);
        }
    }

    const size_t kvrow0 = (size_t)(b * M_KV) * (2 * D_) + h * HD_;
    auto load_kv = [&](int c, int s) {
        const __nv_bfloat16* arr[4] = {
            kvhi + kvrow0 + (size_t)(c * 64) * (2 * D_),
            kvlo + kvrow0 + (size_t)(c * 64) * (2 * D_),
            kvhi + kvrow0 + (size_t)(c * 64) * (2 * D_) + D_,
            kvlo + kvrow0 + (size_t)(c * 64) * (2 * D_) + D_ };
        const u32 stb = sb + AQ_TOT + s * AKV_STAGE;
#pragma unroll
        for (int t = 0; t < 4; t++) {
#pragma unroll
            for (int j = 0; j < 4; j++) {
                int idx = tid + j * 256;
                int r = idx >> 4, c16 = idx & 15;
                cp_async16(stb + t * AKV_TILE + r * SROW_B + c16 * 16,
                           arr[t] + (size_t)r * (2 * D_) + c16 * 8);
            }
        }
    };

    load_kv(0, 0);
    cp_commit();
    cp_wait0();
    __syncthreads();

    float o[16][4];
#pragma unroll
    for (int nt = 0; nt < 16; nt++)
#pragma unroll
        for (int e = 0; e < 4; e++) o[nt][e] = 0.f;
    float m0 = -INFINITY, m1 = -INFINITY, l0 = 0.f, l1 = 0.f;

    for (int c = 0; c < 8; c++) {
        const int s = c & 1;
        if (c + 1 < 8) { load_kv(c + 1, s ^ 1); cp_commit(); }

        const u32 kb = sb + AQ_TOT + s * AKV_STAGE;

        // ---- S = Q @ K^T (3-term split) ----
        float sf[8][4];
#pragma unroll
        for (int t = 0; t < 8; t++)
#pragma unroll
            for (int e = 0; e < 4; e++) sf[t][e] = 0.f;

#pragma unroll
        for (int ks = 0; ks < 8; ks++) {
            u32 ar = sb + (u32)((wid * 16 + (lane & 15)) * SROW_B + (ks * 16 + (lane >> 4) * 8) * 2);
            u32 ah[4], al[4];
            ldmx4(ah[0], ah[1], ah[2], ah[3], ar);
            ldmx4(al[0], al[1], al[2], al[3], ar + AQ_TILE);
#pragma unroll
            for (int np = 0; np < 4; np++) {
                u32 ba = kb + (u32)((np * 16 + (lane & 7) + ((lane >> 4) & 1) * 8) * SROW_B
                                    + (ks * 16 + ((lane >> 3) & 1) * 8) * 2);
                u32 b0, b1, b2, b3, c0, c1, c2, c3;
                ldmx4(b0, b1, b2, b3, ba);               // Khi
                ldmx4(c0, c1, c2, c3, ba + AKV_TILE);    // Klo
                { u32 bb[2] = { b0, b1 }; mma16816(sf[2 * np], ah, bb); mma16816(sf[2 * np], al, bb); }
                { u32 bb[2] = { b2, b3 }; mma16816(sf[2 * np + 1], ah, bb); mma16816(sf[2 * np + 1], al, bb); }
                { u32 bb[2] = { c0, c1 }; mma16816(sf[2 * np], ah, bb); }
                { u32 bb[2] = { c2, c3 }; mma16816(sf[2 * np + 1], ah, bb); }
            }
        }

        // ---- online softmax (rows lr = lane>>2, lr+8; stats shared by 4-lane group) ----
        float tm0 = -INFINITY, tm1 = -INFINITY;
#pragma unroll
        for (int t = 0; t < 8; t++) {
            tm0 = fmaxf(tm0, fmaxf(sf[t][0], sf[t][1]));
            tm1 = fmaxf(tm1, fmaxf(sf[t][2], sf[t][3]));
        }
        tm0 = fmaxf(tm0, __shfl_xor_sync(0xffffffffu, tm0, 1));
        tm0 = fmaxf(tm0, __shfl_xor_sync(0xffffffffu, tm0, 2));
        tm1 = fmaxf(tm1, __shfl_xor_sync(0xffffffffu, tm1, 1));
        tm1 = fmaxf(tm1, __shfl_xor_sync(0xffffffffu, tm1, 2));
        float mn0 = fmaxf(m0, tm0), mn1 = fmaxf(m1, tm1);
        float cr0 = __expf(m0 - mn0), cr1 = __expf(m1 - mn1);
        m0 = mn0; m1 = mn1;
        float ls0 = 0.f, ls1 = 0.f;
#pragma unroll
        for (int t = 0; t < 8; t++) {
            sf[t][0] = __expf(sf[t][0] - mn0);
            sf[t][1] = __expf(sf[t][1] - mn0);
            sf[t][2] = __expf(sf[t][2] - mn1);
            sf[t][3] = __expf(sf[t][3] - mn1);
            ls0 += sf[t][0] + sf[t][1];
            ls1 += sf[t][2] + sf[t][3];
        }
        ls0 += __shfl_xor_sync(0xffffffffu, ls0, 1);
        ls0 += __shfl_xor_sync(0xffffffffu, ls0, 2);
        ls1 += __shfl_xor_sync(0xffffffffu, ls1, 1);
        ls1 += __shfl_xor_sync(0xffffffffu, ls1, 2);
        l0 = l0 * cr0 + ls0;
        l1 = l1 * cr1 + ls1;
#pragma unroll
        for (int nt = 0; nt < 16; nt++) {
            o[nt][0] *= cr0; o[nt][1] *= cr0;
            o[nt][2] *= cr1; o[nt][3] *= cr1;
        }

        // ---- P -> bf16 hi/lo A-fragments (register-to-register) ----
        u32 phi[4][4], plo[4][4];
#pragma unroll
        for (int kt = 0; kt < 4; kt++) {
            float p00 = sf[2 * kt][0], p01 = sf[2 * kt][1];
            float p10 = sf[2 * kt][2], p11 = sf[2 * kt][3];
            float p20 = sf[2 * kt + 1][0], p21 = sf[2 * kt + 1][1];
            float p30 = sf[2 * kt + 1][2], p31 = sf[2 * kt + 1][3];
            phi[kt][0] = bf16x2_pack(p01, p00); plo[kt][0] = bf16x2_residual(phi[kt][0], p00, p01);
            phi[kt][1] = bf16x2_pack(p11, p10); plo[kt][1] = bf16x2_residual(phi[kt][1], p10, p11);
            phi[kt][2] = bf16x2_pack(p21, p20); plo[kt][2] = bf16x2_residual(phi[kt][2], p20, p21);
            phi[kt][3] = bf16x2_pack(p31, p30); plo[kt][3] = bf16x2_residual(phi[kt][3], p30, p31);
        }

        // ---- O += P @ V (3-term split); V via ldmatrix.trans ----
        const u32 vb = kb + 2 * AKV_TILE;
#pragma unroll
        for (int np = 0; np < 8; np++) {
#pragma unroll
            for (int kt = 0; kt < 4; kt++) {
                u32 va = vb + (u32)((kt * 16 + (lane & 15)) * SROW_B + (np * 16 + (lane >> 4) * 8) * 2);
                u32 b0, b1, b2, b3, c0, c1, c2, c3;
                ldmx4t(b0, b1, b2, b3, va);               // Vhi
                ldmx4t(c0, c1, c2, c3, va + AKV_TILE);    // Vlo
                { u32 bb[2] = { b0, b1 }; mma16816(o[2 * np], phi[kt], bb); mma16816(o[2 * np], plo[kt], bb); }
                { u32 bb[2] = { b2, b3 }; mma16816(o[2 * np + 1], phi[kt], bb); mma16816(o[2 * np + 1], plo[kt], bb); }
                { u32 bb[2] = { c0, c1 }; mma16816(o[2 * np], phi[kt], bb); }
                { u32 bb[2] = { c2, c3 }; mma16816(o[2 * np + 1], phi[kt], bb); }
            }
        }

        cp_wait0();
        __syncthreads();
    }

    // ---- normalize + split + write ctx (bf16 hi/lo, ready for O-proj) ----
    float inv0 = 1.0f / l0, inv1 = 1.0f / l1;
    int grow = b * N_Q + q0 + wid * 16 + (lane >> 2);
    int gcol = h * HD_ + 2 * (lane & 3);
#pragma unroll
    for (int nt = 0; nt < 16; nt++) {
        int col = gcol + nt * 8;
        size_t off0 = (size_t)grow * D_ + col;
        size_t off8 = (size_t)(grow + 8) * D_ + col;
        float p0 = o[nt][0] * inv0, p1 = o[nt][1] * inv0;
        u32 hp = bf16x2_pack(p1, p0);
        u32 lp = bf16x2_residual(hp, p0, p1);
        *(u32*)(chi + off0) = hp;
        *(u32*)(clo + off0) = lp;
        p0 = o[nt][2] * inv1; p1 = o[nt][3] * inv1;
        hp = bf16x2_pack(p1, p0);
        lp = bf16x2_residual(hp, p0, p1);
        *(u32*)(chi + off8) = hp;
        *(u32*)(clo + off8) = lp;
    }
}

// ---------------- launch ----------------
extern "C" void kernel_launch(void* const* d_in, const int* in_sizes, int n_in,
                              void* d_out, int out_size)
{
    const float* x       = (const float*)d_in[0];
    const float* context = (const float*)d_in[1];
    const float* wq      = (const float*)d_in[2];
    const float* bq      = (const float*)d_in[3];
    const float* wkv     = (const float*)d_in[4];
    const float* bkv     = (const float*)d_in[5];
    const float* wo      = (const float*)d_in[6];
    const float* bo      = (const float*)d_in[7];
    const float* qns     = (const float*)d_in[8];
    float* out = (float*)d_out;

    float *q, *kv;
    __nv_bfloat16 *ahi, *alo, *qhi, *qlo, *kvhi, *kvlo;
    __nv_bfloat16 *wqhi, *wqlo, *wkvhi, *wkvlo, *wohi, *wolo;
    cudaGetSymbolAddress((void**)&q,     g_q);
    cudaGetSymbolAddress((void**)&kv,    g_kv);
    cudaGetSymbolAddress((void**)&ahi,   g_ahi);
    cudaGetSymbolAddress((void**)&alo,   g_alo);
    cudaGetSymbolAddress((void**)&qhi,   g_qhi);
    cudaGetSymbolAddress((void**)&qlo,   g_qlo);
    cudaGetSymbolAddress((void**)&kvhi,  g_kvhi);
    cudaGetSymbolAddress((void**)&kvlo,  g_kvlo);
    cudaGetSymbolAddress((void**)&wqhi,  g_wqhi);
    cudaGetSymbolAddress((void**)&wqlo,  g_wqlo);
    cudaGetSymbolAddress((void**)&wkvhi, g_wkvhi);
    cudaGetSymbolAddress((void**)&wkvlo, g_wkvlo);
    cudaGetSymbolAddress((void**)&wohi,  g_wohi);
    cudaGetSymbolAddress((void**)&wolo,  g_wolo);

    cudaFuncSetAttribute(gemm_mma, cudaFuncAttributeMaxDynamicSharedMemorySize, GEMM_SMEM);
    cudaFuncSetAttribute(attn_mma, cudaFuncAttributeMaxDynamicSharedMemorySize, ATT_SMEM);

    // weight transpose+split
    tsplit_kernel<<<dim3(D_ / 32, D_ / 32), dim3(32, 8)>>>(wq, wqhi, wqlo, D_, D_);
    tsplit_kernel<<<dim3((2 * D_) / 32, D_ / 32), dim3(32, 8)>>>(wkv, wkvhi, wkvlo, D_, 2 * D_);
    tsplit_kernel<<<dim3(D_ / 32, D_ / 32), dim3(32, 8)>>>(wo, wohi, wolo, D_, D_);

    // Q = x @ wq + bq  -> rmsnorm+scale+split -> qhi/qlo
    {
        int n4 = (B_ * N_Q * D_) / 4;
        split_kernel<<<(n4 + 255) / 256, 256>>>(x, ahi, alo, n4);
        gemm_mma<<<dim3(D_ / 128, (B_ * N_Q) / 128), 256, GEMM_SMEM>>>(
            ahi, alo, wqhi, wqlo, bq, q, B_ * N_Q, D_, D_);
        rmsnorm_split_kernel<<<(B_ * N_Q * H_) / 8, 256>>>(q, qns, qhi, qlo);
    }

    // KV = context @ wkv + bkv -> split -> kvhi/kvlo
    {
        int n4 = (B_ * M_KV * D_) / 4;
        split_kernel<<<(n4 + 255) / 256, 256>>>(context, ahi, alo, n4);
        gemm_mma<<<dim3((2 * D_) / 128, (B_ * M_KV) / 128), 256, GEMM_SMEM>>>(
            ahi, alo, wkvhi, wkvlo, bkv, kv, B_ * M_KV, 2 * D_, D_);
        int k4 = (B_ * M_KV * 2 * D_) / 4;
        split_kernel<<<(k4 + 255) / 256, 256>>>(kv, kvhi, kvlo, k4);
    }

    // attention -> ctx hi/lo directly into ahi/alo
    attn_mma<<<dim3(N_Q / 128, H_, B_), 256, ATT_SMEM>>>(qhi, qlo, kvhi, kvlo, ahi, alo);

    // out = ctx @ wo + bo
    gemm_mma<<<dim3(D_ / 128, (B_ * N_Q) / 128), 256, GEMM_SMEM>>>(
        ahi, alo, wohi, wolo, bo, out, B_ * N_Q, D_, D_);
}

// round 9
// speedup vs baseline: 2.7290x; 1.0179x over previous
#include <cuda_runtime.h>
#include <cuda_bf16.h>
#include <stdint.h>
#include <math.h>

// Problem dims (fixed)
#define B_   2
#define N_Q  5376
#define M_KV 512
#define D_   1536
#define H_   12
#define HD_  128

// ---------------- scratch (device globals: allocation-guard safe) ----------------
__device__ __nv_bfloat16 g_ahi[(size_t)B_ * N_Q * D_];   // activation hi (x, ctx)
__device__ __nv_bfloat16 g_alo[(size_t)B_ * N_Q * D_];   // activation lo
__device__ __nv_bfloat16 g_qhi[(size_t)B_ * N_Q * D_];
__device__ __nv_bfloat16 g_qlo[(size_t)B_ * N_Q * D_];
__device__ __nv_bfloat16 g_kvhi[(size_t)B_ * M_KV * 2 * D_];
__device__ __nv_bfloat16 g_kvlo[(size_t)B_ * M_KV * 2 * D_];
__device__ __nv_bfloat16 g_wqhi[(size_t)D_ * D_];
__device__ __nv_bfloat16 g_wqlo[(size_t)D_ * D_];
__device__ __nv_bfloat16 g_wkvhi[(size_t)2 * D_ * D_];
__device__ __nv_bfloat16 g_wkvlo[(size_t)2 * D_ * D_];
__device__ __nv_bfloat16 g_wohi[(size_t)D_ * D_];
__device__ __nv_bfloat16 g_wolo[(size_t)D_ * D_];

// ---------------- helpers ----------------
typedef unsigned long long u64;
typedef unsigned int u32;

__device__ __forceinline__ u32 smem_u32(const void* p) {
    u32 a;
    asm("{ .reg .u64 t; cvta.to.shared.u64 t, %1; cvt.u32.u64 %0, t; }" : "=r"(a) : "l"(p));
    return a;
}
__device__ __forceinline__ void cp_async16(u32 dst, const void* src) {
    asm volatile("cp.async.cg.shared.global [%0], [%1], 16;" :: "r"(dst), "l"(src) : "memory");
}
__device__ __forceinline__ void cp_commit() {
    asm volatile("cp.async.commit_group;" ::: "memory");
}
__device__ __forceinline__ void cp_wait0() {
    asm volatile("cp.async.wait_group 0;" ::: "memory");
}
__device__ __forceinline__ void ldmx4(u32& r0, u32& r1, u32& r2, u32& r3, u32 addr) {
    asm volatile("ldmatrix.sync.aligned.m8n8.x4.shared.b16 {%0,%1,%2,%3}, [%4];"
                 : "=r"(r0), "=r"(r1), "=r"(r2), "=r"(r3) : "r"(addr));
}
__device__ __forceinline__ void ldmx4t(u32& r0, u32& r1, u32& r2, u32& r3, u32 addr) {
    asm volatile("ldmatrix.sync.aligned.m8n8.x4.trans.shared.b16 {%0,%1,%2,%3}, [%4];"
                 : "=r"(r0), "=r"(r1), "=r"(r2), "=r"(r3) : "r"(addr));
}
__device__ __forceinline__ void ldmx2(u32& r0, u32& r1, u32 addr) {
    asm volatile("ldmatrix.sync.aligned.m8n8.x2.shared.b16 {%0,%1}, [%2];"
                 : "=r"(r0), "=r"(r1) : "r"(addr));
}
__device__ __forceinline__ void mma16816(float* c, const u32* a, const u32* b) {
    asm volatile(
        "mma.sync.aligned.m16n8k16.row.col.f32.bf16.bf16.f32 "
        "{%0,%1,%2,%3}, {%4,%5,%6,%7}, {%8,%9}, {%0,%1,%2,%3};"
        : "+f"(c[0]), "+f"(c[1]), "+f"(c[2]), "+f"(c[3])
        : "r"(a[0]), "r"(a[1]), "r"(a[2]), "r"(a[3]), "r"(b[0]), "r"(b[1]));
}
__device__ __forceinline__ u32 bf16x2_pack(float hi, float lo) {
    u32 r; asm("cvt.rn.bf16x2.f32 %0, %1, %2;" : "=r"(r) : "f"(hi), "f"(lo)); return r;
}
__device__ __forceinline__ u32 bf16x2_residual(u32 hi_packed, float p0, float p1) {
    float f0 = __uint_as_float(hi_packed << 16);
    float f1 = __uint_as_float(hi_packed & 0xFFFF0000u);
    return bf16x2_pack(p1 - f1, p0 - f0);
}

// ---------------- prep: elementwise fp32 -> (hi, lo) bf16 ----------------
struct alignas(8) B4 { __nv_bfloat16 v[4]; };

__global__ void split_kernel(const float* __restrict__ in, __nv_bfloat16* __restrict__ hi,
                             __nv_bfloat16* __restrict__ lo, int n4)
{
    int i = blockIdx.x * blockDim.x + threadIdx.x;
    if (i >= n4) return;
    float4 v = ((const float4*)in)[i];
    B4 hb, lb;
    float f[4] = { v.x, v.y, v.z, v.w };
#pragma unroll
    for (int j = 0; j < 4; j++) {
        __nv_bfloat16 h = __float2bfloat16(f[j]);
        hb.v[j] = h;
        lb.v[j] = __float2bfloat16(f[j] - __bfloat162float(h));
    }
    ((B4*)hi)[i] = hb;
    ((B4*)lo)[i] = lb;
}

// ---------------- prep: transpose + split, fp32 [K,N] -> bf16 [N,K] hi/lo ----------------
__global__ void tsplit_kernel(const float* __restrict__ in, __nv_bfloat16* __restrict__ hi,
                              __nv_bfloat16* __restrict__ lo, int K, int N)
{
    __shared__ float t[32][33];
    int n0 = blockIdx.x * 32, k0 = blockIdx.y * 32;
    int tx = threadIdx.x, ty = threadIdx.y;      // 32 x 8
#pragma unroll
    for (int j = 0; j < 4; j++)
        t[ty + 8 * j][tx] = in[(size_t)(k0 + ty + 8 * j) * N + n0 + tx];
    __syncthreads();
#pragma unroll
    for (int j = 0; j < 4; j++) {
        int r = ty + 8 * j;
        float v = t[tx][r];
        __nv_bfloat16 h = __float2bfloat16(v);
        size_t o = (size_t)(n0 + r) * K + k0 + tx;
        hi[o] = h;
        lo[o] = __float2bfloat16(v - __bfloat162float(h));
    }
}

// ---------------- shared GEMM mainloop: split-bf16 via mma.sync ----------------
// C_tile[128,128] = (Ahi+Alo)[M,K] @ (Bhi+Blo)^T (B stored [N,K] K-major), 3-term.
#define GROW_B   80
#define GTILE_B  (128 * GROW_B)
#define GSTAGE_B (4 * GTILE_B)
#define GEMM_SMEM (2 * GSTAGE_B)

__device__ __forceinline__ void gemm_mainloop(
    const __nv_bfloat16* __restrict__ Ahi, const __nv_bfloat16* __restrict__ Alo,
    const __nv_bfloat16* __restrict__ Bhi, const __nv_bfloat16* __restrict__ Blo,
    char* sm, int K, int row0, int col0, float (&acc)[4][4][4])
{
    const u32 sbase = smem_u32(sm);
    const int tid = threadIdx.x;
    const int wid = tid >> 5, lane = tid & 31;
    const int wm = wid >> 2;
    const int wn = wid & 3;

    const int ku4 = K >> 3;
    const uint4* srcs[4] = {
        (const uint4*)Ahi + (size_t)row0 * ku4,
        (const uint4*)Alo + (size_t)row0 * ku4,
        (const uint4*)Bhi + (size_t)col0 * ku4,
        (const uint4*)Blo + (size_t)col0 * ku4 };

    const int lr0 = tid >> 2;
    const int lc = tid & 3;

    auto load_chunk = [&](int c, int s) {
        const u32 stb = sbase + s * GSTAGE_B;
#pragma unroll
        for (int t = 0; t < 4; t++) {
            const uint4* gp = srcs[t] + (size_t)c * 4 + lc;
#pragma unroll
            for (int j = 0; j < 2; j++) {
                int r = lr0 + j * 64;
                cp_async16(stb + t * GTILE_B + r * GROW_B + lc * 16,
                           gp + (size_t)r * ku4);
            }
        }
        cp_commit();
    };

#pragma unroll
    for (int i = 0; i < 4; i++)
#pragma unroll
        for (int j = 0; j < 4; j++)
#pragma unroll
            for (int e = 0; e < 4; e++) acc[i][j][e] = 0.f;

    load_chunk(0, 0);
    cp_wait0();
    __syncthreads();

    const int NC = K >> 5;
    for (int c = 0; c < NC; c++) {
        const int s = c & 1;
        if (c + 1 < NC) load_chunk(c + 1, s ^ 1);

        const u32 abase = sbase + s * GSTAGE_B;
        const u32 bbase = abase + 2 * GTILE_B;
#pragma unroll
        for (int ks = 0; ks < 2; ks++) {
            u32 ahi[4][4], alo[4][4];
            const u32 acol2 = (ks * 16 + ((lane >> 4) << 3)) * 2;
#pragma unroll
            for (int mt = 0; mt < 4; mt++) {
                u32 ad = abase + (u32)((wm * 64 + mt * 16 + (lane & 15)) * GROW_B) + acol2;
                ldmx4(ahi[mt][0], ahi[mt][1], ahi[mt][2], ahi[mt][3], ad);
                ldmx4(alo[mt][0], alo[mt][1], alo[mt][2], alo[mt][3], ad + GTILE_B);
            }
            const u32 bcol2 = (ks * 16 + (((lane >> 3) & 1) << 3)) * 2;
#pragma unroll
            for (int nt = 0; nt < 4; nt++) {
                u32 bh[2], bl[2];
                u32 bd = bbase + (u32)((wn * 32 + nt * 8 + (lane & 7)) * GROW_B) + bcol2;
                ldmx2(bh[0], bh[1], bd);
                ldmx2(bl[0], bl[1], bd + GTILE_B);
#pragma unroll
                for (int mt = 0; mt < 4; mt++) {
                    mma16816(acc[mt][nt], ahi[mt], bh);
                    mma16816(acc[mt][nt], ahi[mt], bl);
                    mma16816(acc[mt][nt], alo[mt], bh);
                }
            }
        }
        cp_wait0();
        __syncthreads();
    }
}

// ---------------- GEMM, fp32 + bias epilogue (O-proj) ----------------
__global__ __launch_bounds__(256, 2)
void gemm_mma(const __nv_bfloat16* __restrict__ Ahi, const __nv_bfloat16* __restrict__ Alo,
              const __nv_bfloat16* __restrict__ Bhi, const __nv_bfloat16* __restrict__ Blo,
              const float* __restrict__ bias, float* __restrict__ C,
              int M, int N, int K)
{
    extern __shared__ __align__(16) char sm[];
    const int tid = threadIdx.x;
    const int wid = tid >> 5, lane = tid & 31;
    const int wm = wid >> 2, wn = wid & 3;
    const int row0 = blockIdx.y * 128, col0 = blockIdx.x * 128;

    float acc[4][4][4];
    gemm_mainloop(Ahi, Alo, Bhi, Blo, sm, K, row0, col0, acc);

    const int lr = lane >> 2;
    const int ln = (lane & 3) * 2;
#pragma unroll
    for (int mt = 0; mt < 4; mt++) {
#pragma unroll
        for (int nt = 0; nt < 4; nt++) {
            int col = col0 + wn * 32 + nt * 8 + ln;
            float2 bv = *(const float2*)(bias + col);
            int r0 = row0 + wm * 64 + mt * 16 + lr;
            float2 v0 = { acc[mt][nt][0] + bv.x, acc[mt][nt][1] + bv.y };
            float2 v1 = { acc[mt][nt][2] + bv.x, acc[mt][nt][3] + bv.y };
            *(float2*)(C + (size_t)r0 * N + col) = v0;
            *(float2*)(C + (size_t)(r0 + 8) * N + col) = v1;
        }
    }
}

// ---------------- GEMM, bias + hi/lo bf16 epilogue (KV-proj) ----------------
__global__ __launch_bounds__(256, 2)
void gemm_kv_fused(const __nv_bfloat16* __restrict__ Ahi, const __nv_bfloat16* __restrict__ Alo,
                   const __nv_bfloat16* __restrict__ Bhi, const __nv_bfloat16* __restrict__ Blo,
                   const float* __restrict__ bias,
                   __nv_bfloat16* __restrict__ Chi, __nv_bfloat16* __restrict__ Clo,
                   int M, int N, int K)
{
    extern __shared__ __align__(16) char sm[];
    const int tid = threadIdx.x;
    const int wid = tid >> 5, lane = tid & 31;
    const int wm = wid >> 2, wn = wid & 3;
    const int row0 = blockIdx.y * 128, col0 = blockIdx.x * 128;

    float acc[4][4][4];
    gemm_mainloop(Ahi, Alo, Bhi, Blo, sm, K, row0, col0, acc);

    const int lr = lane >> 2;
    const int ln = (lane & 3) * 2;
#pragma unroll
    for (int mt = 0; mt < 4; mt++) {
#pragma unroll
        for (int nt = 0; nt < 4; nt++) {
            int col = col0 + wn * 32 + nt * 8 + ln;
            float2 bv = *(const float2*)(bias + col);
            int r0 = row0 + wm * 64 + mt * 16 + lr;
            float v0 = acc[mt][nt][0] + bv.x, v1 = acc[mt][nt][1] + bv.y;
            float v2 = acc[mt][nt][2] + bv.x, v3 = acc[mt][nt][3] + bv.y;
            u32 hp = bf16x2_pack(v1, v0);
            u32 lp = bf16x2_residual(hp, v0, v1);
            *(u32*)(Chi + (size_t)r0 * N + col) = hp;
            *(u32*)(Clo + (size_t)r0 * N + col) = lp;
            hp = bf16x2_pack(v3, v2);
            lp = bf16x2_residual(hp, v2, v3);
            *(u32*)(Chi + (size_t)(r0 + 8) * N + col) = hp;
            *(u32*)(Clo + (size_t)(r0 + 8) * N + col) = lp;
        }
    }
}

// ---------------- GEMM, bias + RMSNorm + 1/sqrt(HD) + split epilogue (Q-proj) ----------------
// Col tile (128) == one head (HD_=128): row sum-of-squares is CTA-local.
__global__ __launch_bounds__(256, 2)
void gemm_q_fused(const __nv_bfloat16* __restrict__ Ahi, const __nv_bfloat16* __restrict__ Alo,
                  const __nv_bfloat16* __restrict__ Bhi, const __nv_bfloat16* __restrict__ Blo,
                  const float* __restrict__ bias, const float* __restrict__ gscale,
                  __nv_bfloat16* __restrict__ Chi, __nv_bfloat16* __restrict__ Clo,
                  int M, int N, int K)
{
    extern __shared__ __align__(16) char sm[];
    const int tid = threadIdx.x;
    const int wid = tid >> 5, lane = tid & 31;
    const int wm = wid >> 2, wn = wid & 3;
    const int row0 = blockIdx.y * 128, col0 = blockIdx.x * 128;

    float acc[4][4][4];
    gemm_mainloop(Ahi, Alo, Bhi, Blo, sm, K, row0, col0, acc);

    const int lr = lane >> 2;
    const int ln = (lane & 3) * 2;

    // bias add + per-thread partial sum-of-squares for its 8 rows (2 per mt)
    float ss[4][2];
#pragma unroll
    for (int mt = 0; mt < 4; mt++) { ss[mt][0] = 0.f; ss[mt][1] = 0.f; }
#pragma unroll
    for (int nt = 0; nt < 4; nt++) {
        int col = col0 + wn * 32 + nt * 8 + ln;
        float2 bv = *(const float2*)(bias + col);
#pragma unroll
        for (int mt = 0; mt < 4; mt++) {
            acc[mt][nt][0] += bv.x; acc[mt][nt][1] += bv.y;
            acc[mt][nt][2] += bv.x; acc[mt][nt][3] += bv.y;
            ss[mt][0] += acc[mt][nt][0] * acc[mt][nt][0] + acc[mt][nt][1] * acc[mt][nt][1];
            ss[mt][1] += acc[mt][nt][2] * acc[mt][nt][2] + acc[mt][nt][3] * acc[mt][nt][3];
        }
    }
    // quad reduce (cols within warp) -> 32-col partials
#pragma unroll
    for (int mt = 0; mt < 4; mt++) {
#pragma unroll
        for (int half = 0; half < 2; half++) {
            ss[mt][half] += __shfl_xor_sync(0xffffffffu, ss[mt][half], 1);
            ss[mt][half] += __shfl_xor_sync(0xffffffffu, ss[mt][half], 2);
        }
    }
    // cross-warp (wn) reduce via smem: ssum[wn][128 local rows]
    float* ssum = (float*)sm;
    if ((lane & 3) == 0) {
#pragma unroll
        for (int mt = 0; mt < 4; mt++) {
            int lrow = wm * 64 + mt * 16 + lr;
            ssum[wn * 128 + lrow] = ss[mt][0];
            ssum[wn * 128 + lrow + 8] = ss[mt][1];
        }
    }
    __syncthreads();

    const float QK_SCALE = 0.08838834764831845f;  // 1/sqrt(HD)
#pragma unroll
    for (int mt = 0; mt < 4; mt++) {
        int lrow = wm * 64 + mt * 16 + lr;
        float s0 = ssum[lrow] + ssum[128 + lrow] + ssum[256 + lrow] + ssum[384 + lrow];
        float s1 = ssum[lrow + 8] + ssum[128 + lrow + 8] + ssum[256 + lrow + 8] + ssum[384 + lrow + 8];
        float r0 = rsqrtf(s0 * (1.0f / 128.0f) + 1e-6f) * QK_SCALE;
        float r1 = rsqrtf(s1 * (1.0f / 128.0f) + 1e-6f) * QK_SCALE;
        int grow = row0 + lrow;
#pragma unroll
        for (int nt = 0; nt < 4; nt++) {
            int hdidx = wn * 32 + nt * 8 + ln;           // index within head
            float2 gs = *(const float2*)(gscale + hdidx);
            int col = col0 + hdidx;
            float v0 = acc[mt][nt][0] * r0 * gs.x, v1 = acc[mt][nt][1] * r0 * gs.y;
            float v2 = acc[mt][nt][2] * r1 * gs.x, v3 = acc[mt][nt][3] * r1 * gs.y;
            u32 hp = bf16x2_pack(v1, v0);
            u32 lp = bf16x2_residual(hp, v0, v1);
            *(u32*)(Chi + (size_t)grow * N + col) = hp;
            *(u32*)(Clo + (size_t)grow * N + col) = lp;
            hp = bf16x2_pack(v3, v2);
            lp = bf16x2_residual(hp, v2, v3);
            *(u32*)(Chi + (size_t)(grow + 8) * N + col) = hp;
            *(u32*)(Clo + (size_t)(grow + 8) * N + col) = lp;
        }
    }
}

// ---------------- Flash attention via mma.sync, split-bf16 both GEMMs ----------------
#define SROW_B 272
#define AQ_TILE (128 * SROW_B)
#define AKV_TILE (64 * SROW_B)
#define AQ_TOT (2 * AQ_TILE)
#define AKV_STAGE (4 * AKV_TILE)
#define ATT_SMEM (AQ_TOT + 2 * AKV_STAGE)  // 208896

__global__ __launch_bounds__(256, 1)
void attn_mma(const __nv_bfloat16* __restrict__ qhi, const __nv_bfloat16* __restrict__ qlo,
              const __nv_bfloat16* __restrict__ kvhi, const __nv_bfloat16* __restrict__ kvlo,
              __nv_bfloat16* __restrict__ chi, __nv_bfloat16* __restrict__ clo)
{
    extern __shared__ __align__(16) char sm[];
    const u32 sb = smem_u32(sm);
    const int tid = threadIdx.x, wid = tid >> 5, lane = tid & 31;
    const int q0 = blockIdx.x * 128, h = blockIdx.y, b = blockIdx.z;

    {
        const __nv_bfloat16* s0 = qhi + (size_t)(b * N_Q + q0) * D_ + h * HD_;
        const __nv_bfloat16* s1 = qlo + (size_t)(b * N_Q + q0) * D_ + h * HD_;
#pragma unroll
        for (int j = 0; j < 8; j++) {
            int idx = tid + j * 256;
            int r = idx >> 4, c = idx & 15;
            cp_async16(sb + r * SROW_B + c * 16, s0 + (size_t)r * D_ + c * 8);
            cp_async16(sb + AQ_TILE + r * SROW_B + c * 16, s1 + (size_t)r * D_ + c * 8);
        }
    }

    const size_t kvrow0 = (size_t)(b * M_KV) * (2 * D_) + h * HD_;
    auto load_kv = [&](int c, int s) {
        const __nv_bfloat16* arr[4] = {
            kvhi + kvrow0 + (size_t)(c * 64) * (2 * D_),
            kvlo + kvrow0 + (size_t)(c * 64) * (2 * D_),
            kvhi + kvrow0 + (size_t)(c * 64) * (2 * D_) + D_,
            kvlo + kvrow0 + (size_t)(c * 64) * (2 * D_) + D_ };
        const u32 stb = sb + AQ_TOT + s * AKV_STAGE;
#pragma unroll
        for (int t = 0; t < 4; t++) {
#pragma unroll
            for (int j = 0; j < 4; j++) {
                int idx = tid + j * 256;
                int r = idx >> 4, c16 = idx & 15;
                cp_async16(stb + t * AKV_TILE + r * SROW_B + c16 * 16,
                           arr[t] + (size_t)r * (2 * D_) + c16 * 8);
            }
        }
    };

    load_kv(0, 0);
    cp_commit();
    cp_wait0();
    __syncthreads();

    float o[16][4];
#pragma unroll
    for (int nt = 0; nt < 16; nt++)
#pragma unroll
        for (int e = 0; e < 4; e++) o[nt][e] = 0.f;
    float m0 = -INFINITY, m1 = -INFINITY, l0 = 0.f, l1 = 0.f;

    for (int c = 0; c < 8; c++) {
        const int s = c & 1;
        if (c + 1 < 8) { load_kv(c + 1, s ^ 1); cp_commit(); }

        const u32 kb = sb + AQ_TOT + s * AKV_STAGE;

        float sf[8][4];
#pragma unroll
        for (int t = 0; t < 8; t++)
#pragma unroll
            for (int e = 0; e < 4; e++) sf[t][e] = 0.f;

#pragma unroll
        for (int ks = 0; ks < 8; ks++) {
            u32 ar = sb + (u32)((wid * 16 + (lane & 15)) * SROW_B + (ks * 16 + (lane >> 4) * 8) * 2);
            u32 ah[4], al[4];
            ldmx4(ah[0], ah[1], ah[2], ah[3], ar);
            ldmx4(al[0], al[1], al[2], al[3], ar + AQ_TILE);
#pragma unroll
            for (int np = 0; np < 4; np++) {
                u32 ba = kb + (u32)((np * 16 + (lane & 7) + ((lane >> 4) & 1) * 8) * SROW_B
                                    + (ks * 16 + ((lane >> 3) & 1) * 8) * 2);
                u32 b0, b1, b2, b3, c0, c1, c2, c3;
                ldmx4(b0, b1, b2, b3, ba);
                ldmx4(c0, c1, c2, c3, ba + AKV_TILE);
                { u32 bb[2] = { b0, b1 }; mma16816(sf[2 * np], ah, bb); mma16816(sf[2 * np], al, bb); }
                { u32 bb[2] = { b2, b3 }; mma16816(sf[2 * np + 1], ah, bb); mma16816(sf[2 * np + 1], al, bb); }
                { u32 bb[2] = { c0, c1 }; mma16816(sf[2 * np], ah, bb); }
                { u32 bb[2] = { c2, c3 }; mma16816(sf[2 * np + 1], ah, bb); }
            }
        }

        float tm0 = -INFINITY, tm1 = -INFINITY;
#pragma unroll
        for (int t = 0; t < 8; t++) {
            tm0 = fmaxf(tm0, fmaxf(sf[t][0], sf[t][1]));
            tm1 = fmaxf(tm1, fmaxf(sf[t][2], sf[t][3]));
        }
        tm0 = fmaxf(tm0, __shfl_xor_sync(0xffffffffu, tm0, 1));
        tm0 = fmaxf(tm0, __shfl_xor_sync(0xffffffffu, tm0, 2));
        tm1 = fmaxf(tm1, __shfl_xor_sync(0xffffffffu, tm1, 1));
        tm1 = fmaxf(tm1, __shfl_xor_sync(0xffffffffu, tm1, 2));
        float mn0 = fmaxf(m0, tm0), mn1 = fmaxf(m1, tm1);
        float cr0 = __expf(m0 - mn0), cr1 = __expf(m1 - mn1);
        m0 = mn0; m1 = mn1;
        float ls0 = 0.f, ls1 = 0.f;
#pragma unroll
        for (int t = 0; t < 8; t++) {
            sf[t][0] = __expf(sf[t][0] - mn0);
            sf[t][1] = __expf(sf[t][1] - mn0);
            sf[t][2] = __expf(sf[t][2] - mn1);
            sf[t][3] = __expf(sf[t][3] - mn1);
            ls0 += sf[t][0] + sf[t][1];
            ls1 += sf[t][2] + sf[t][3];
        }
        ls0 += __shfl_xor_sync(0xffffffffu, ls0, 1);
        ls0 += __shfl_xor_sync(0xffffffffu, ls0, 2);
        ls1 += __shfl_xor_sync(0xffffffffu, ls1, 1);
        ls1 += __shfl_xor_sync(0xffffffffu, ls1, 2);
        l0 = l0 * cr0 + ls0;
        l1 = l1 * cr1 + ls1;
#pragma unroll
        for (int nt = 0; nt < 16; nt++) {
            o[nt][0] *= cr0; o[nt][1] *= cr0;
            o[nt][2] *= cr1; o[nt][3] *= cr1;
        }

        u32 phi[4][4], plo[4][4];
#pragma unroll
        for (int kt = 0; kt < 4; kt++) {
            float p00 = sf[2 * kt][0], p01 = sf[2 * kt][1];
            float p10 = sf[2 * kt][2], p11 = sf[2 * kt][3];
            float p20 = sf[2 * kt + 1][0], p21 = sf[2 * kt + 1][1];
            float p30 = sf[2 * kt + 1][2], p31 = sf[2 * kt + 1][3];
            phi[kt][0] = bf16x2_pack(p01, p00); plo[kt][0] = bf16x2_residual(phi[kt][0], p00, p01);
            phi[kt][1] = bf16x2_pack(p11, p10); plo[kt][1] = bf16x2_residual(phi[kt][1], p10, p11);
            phi[kt][2] = bf16x2_pack(p21, p20); plo[kt][2] = bf16x2_residual(phi[kt][2], p20, p21);
            phi[kt][3] = bf16x2_pack(p31, p30); plo[kt][3] = bf16x2_residual(phi[kt][3], p30, p31);
        }

        const u32 vb = kb + 2 * AKV_TILE;
#pragma unroll
        for (int np = 0; np < 8; np++) {
#pragma unroll
            for (int kt = 0; kt < 4; kt++) {
                u32 va = vb + (u32)((kt * 16 + (lane & 15)) * SROW_B + (np * 16 + (lane >> 4) * 8) * 2);
                u32 b0, b1, b2, b3, c0, c1, c2, c3;
                ldmx4t(b0, b1, b2, b3, va);
                ldmx4t(c0, c1, c2, c3, va + AKV_TILE);
                { u32 bb[2] = { b0, b1 }; mma16816(o[2 * np], phi[kt], bb); mma16816(o[2 * np], plo[kt], bb); }
                { u32 bb[2] = { b2, b3 }; mma16816(o[2 * np + 1], phi[kt], bb); mma16816(o[2 * np + 1], plo[kt], bb); }
                { u32 bb[2] = { c0, c1 }; mma16816(o[2 * np], phi[kt], bb); }
                { u32 bb[2] = { c2, c3 }; mma16816(o[2 * np + 1], phi[kt], bb); }
            }
        }

        cp_wait0();
        __syncthreads();
    }

    float inv0 = 1.0f / l0, inv1 = 1.0f / l1;
    int grow = b * N_Q + q0 + wid * 16 + (lane >> 2);
    int gcol = h * HD_ + 2 * (lane & 3);
#pragma unroll
    for (int nt = 0; nt < 16; nt++) {
        int col = gcol + nt * 8;
        size_t off0 = (size_t)grow * D_ + col;
        size_t off8 = (size_t)(grow + 8) * D_ + col;
        float p0 = o[nt][0] * inv0, p1 = o[nt][1] * inv0;
        u32 hp = bf16x2_pack(p1, p0);
        u32 lp = bf16x2_residual(hp, p0, p1);
        *(u32*)(chi + off0) = hp;
        *(u32*)(clo + off0) = lp;
        p0 = o[nt][2] * inv1; p1 = o[nt][3] * inv1;
        hp = bf16x2_pack(p1, p0);
        lp = bf16x2_residual(hp, p0, p1);
        *(u32*)(chi + off8) = hp;
        *(u32*)(clo + off8) = lp;
    }
}

// ---------------- launch ----------------
extern "C" void kernel_launch(void* const* d_in, const int* in_sizes, int n_in,
                              void* d_out, int out_size)
{
    const float* x       = (const float*)d_in[0];
    const float* context = (const float*)d_in[1];
    const float* wq      = (const float*)d_in[2];
    const float* bq      = (const float*)d_in[3];
    const float* wkv     = (const float*)d_in[4];
    const float* bkv     = (const float*)d_in[5];
    const float* wo      = (const float*)d_in[6];
    const float* bo      = (const float*)d_in[7];
    const float* qns     = (const float*)d_in[8];
    float* out = (float*)d_out;

    __nv_bfloat16 *ahi, *alo, *qhi, *qlo, *kvhi, *kvlo;
    __nv_bfloat16 *wqhi, *wqlo, *wkvhi, *wkvlo, *wohi, *wolo;
    cudaGetSymbolAddress((void**)&ahi,   g_ahi);
    cudaGetSymbolAddress((void**)&alo,   g_alo);
    cudaGetSymbolAddress((void**)&qhi,   g_qhi);
    cudaGetSymbolAddress((void**)&qlo,   g_qlo);
    cudaGetSymbolAddress((void**)&kvhi,  g_kvhi);
    cudaGetSymbolAddress((void**)&kvlo,  g_kvlo);
    cudaGetSymbolAddress((void**)&wqhi,  g_wqhi);
    cudaGetSymbolAddress((void**)&wqlo,  g_wqlo);
    cudaGetSymbolAddress((void**)&wkvhi, g_wkvhi);
    cudaGetSymbolAddress((void**)&wkvlo, g_wkvlo);
    cudaGetSymbolAddress((void**)&wohi,  g_wohi);
    cudaGetSymbolAddress((void**)&wolo,  g_wolo);

    cudaFuncSetAttribute(gemm_mma, cudaFuncAttributeMaxDynamicSharedMemorySize, GEMM_SMEM);
    cudaFuncSetAttribute(gemm_q_fused, cudaFuncAttributeMaxDynamicSharedMemorySize, GEMM_SMEM);
    cudaFuncSetAttribute(gemm_kv_fused, cudaFuncAttributeMaxDynamicSharedMemorySize, GEMM_SMEM);
    cudaFuncSetAttribute(attn_mma, cudaFuncAttributeMaxDynamicSharedMemorySize, ATT_SMEM);

    // weight transpose+split
    tsplit_kernel<<<dim3(D_ / 32, D_ / 32), dim3(32, 8)>>>(wq, wqhi, wqlo, D_, D_);
    tsplit_kernel<<<dim3((2 * D_) / 32, D_ / 32), dim3(32, 8)>>>(wkv, wkvhi, wkvlo, D_, 2 * D_);
    tsplit_kernel<<<dim3(D_ / 32, D_ / 32), dim3(32, 8)>>>(wo, wohi, wolo, D_, D_);

    // Q = rmsnorm(x @ wq + bq) * gscale * 1/sqrt(HD) -> qhi/qlo   (fused epilogue)
    {
        int n4 = (B_ * N_Q * D_) / 4;
        split_kernel<<<(n4 + 255) / 256, 256>>>(x, ahi, alo, n4);
        gemm_q_fused<<<dim3(D_ / 128, (B_ * N_Q) / 128), 256, GEMM_SMEM>>>(
            ahi, alo, wqhi, wqlo, bq, qns, qhi, qlo, B_ * N_Q, D_, D_);
    }

    // KV = context @ wkv + bkv -> kvhi/kvlo   (fused epilogue)
    {
        int n4 = (B_ * M_KV * D_) / 4;
        split_kernel<<<(n4 + 255) / 256, 256>>>(context, ahi, alo, n4);
        gemm_kv_fused<<<dim3((2 * D_) / 128, (B_ * M_KV) / 128), 256, GEMM_SMEM>>>(
            ahi, alo, wkvhi, wkvlo, bkv, kvhi, kvlo, B_ * M_KV, 2 * D_, D_);
    }

    // attention -> ctx hi/lo directly into ahi/alo
    attn_mma<<<dim3(N_Q / 128, H_, B_), 256, ATT_SMEM>>>(qhi, qlo, kvhi, kvlo, ahi, alo);

    // out = ctx @ wo + bo
    gemm_mma<<<dim3(D_ / 128, (B_ * N_Q) / 128), 256, GEMM_SMEM>>>(
        ahi, alo, wohi, wolo, bo, out, B_ * N_Q, D_, D_);
}

// round 10
// speedup vs baseline: 2.7324x; 1.0013x over previous
#include <cuda_runtime.h>
#include <cuda_bf16.h>
#include <stdint.h>
#include <math.h>

// Problem dims (fixed)
#define B_   2
#define N_Q  5376
#define M_KV 512
#define D_   1536
#define H_   12
#define HD_  128

// ---------------- scratch (device globals: allocation-guard safe) ----------------
__device__ __nv_bfloat16 g_ahi[(size_t)B_ * N_Q * D_];   // activation hi (x, ctx)
__device__ __nv_bfloat16 g_alo[(size_t)B_ * N_Q * D_];   // activation lo
__device__ __nv_bfloat16 g_chi[(size_t)B_ * M_KV * D_];  // context hi
__device__ __nv_bfloat16 g_clo[(size_t)B_ * M_KV * D_];  // context lo
__device__ __nv_bfloat16 g_qhi[(size_t)B_ * N_Q * D_];
__device__ __nv_bfloat16 g_qlo[(size_t)B_ * N_Q * D_];
__device__ __nv_bfloat16 g_kvhi[(size_t)B_ * M_KV * 2 * D_];
__device__ __nv_bfloat16 g_kvlo[(size_t)B_ * M_KV * 2 * D_];
__device__ __nv_bfloat16 g_wqhi[(size_t)D_ * D_];
__device__ __nv_bfloat16 g_wqlo[(size_t)D_ * D_];
__device__ __nv_bfloat16 g_wkvhi[(size_t)2 * D_ * D_];
__device__ __nv_bfloat16 g_wkvlo[(size_t)2 * D_ * D_];
__device__ __nv_bfloat16 g_wohi[(size_t)D_ * D_];
__device__ __nv_bfloat16 g_wolo[(size_t)D_ * D_];

// ---------------- helpers ----------------
typedef unsigned long long u64;
typedef unsigned int u32;

__device__ __forceinline__ u32 smem_u32(const void* p) {
    u32 a;
    asm("{ .reg .u64 t; cvta.to.shared.u64 t, %1; cvt.u32.u64 %0, t; }" : "=r"(a) : "l"(p));
    return a;
}
__device__ __forceinline__ void cp_async16(u32 dst, const void* src) {
    asm volatile("cp.async.cg.shared.global [%0], [%1], 16;" :: "r"(dst), "l"(src) : "memory");
}
__device__ __forceinline__ void cp_commit() {
    asm volatile("cp.async.commit_group;" ::: "memory");
}
__device__ __forceinline__ void cp_wait0() {
    asm volatile("cp.async.wait_group 0;" ::: "memory");
}
__device__ __forceinline__ void ldmx4(u32& r0, u32& r1, u32& r2, u32& r3, u32 addr) {
    asm volatile("ldmatrix.sync.aligned.m8n8.x4.shared.b16 {%0,%1,%2,%3}, [%4];"
                 : "=r"(r0), "=r"(r1), "=r"(r2), "=r"(r3) : "r"(addr));
}
__device__ __forceinline__ void ldmx4t(u32& r0, u32& r1, u32& r2, u32& r3, u32 addr) {
    asm volatile("ldmatrix.sync.aligned.m8n8.x4.trans.shared.b16 {%0,%1,%2,%3}, [%4];"
                 : "=r"(r0), "=r"(r1), "=r"(r2), "=r"(r3) : "r"(addr));
}
__device__ __forceinline__ void ldmx2(u32& r0, u32& r1, u32 addr) {
    asm volatile("ldmatrix.sync.aligned.m8n8.x2.shared.b16 {%0,%1}, [%2];"
                 : "=r"(r0), "=r"(r1) : "r"(addr));
}
__device__ __forceinline__ void mma16816(float* c, const u32* a, const u32* b) {
    asm volatile(
        "mma.sync.aligned.m16n8k16.row.col.f32.bf16.bf16.f32 "
        "{%0,%1,%2,%3}, {%4,%5,%6,%7}, {%8,%9}, {%0,%1,%2,%3};"
        : "+f"(c[0]), "+f"(c[1]), "+f"(c[2]), "+f"(c[3])
        : "r"(a[0]), "r"(a[1]), "r"(a[2]), "r"(a[3]), "r"(b[0]), "r"(b[1]));
}
__device__ __forceinline__ u32 bf16x2_pack(float hi, float lo) {
    u32 r; asm("cvt.rn.bf16x2.f32 %0, %1, %2;" : "=r"(r) : "f"(hi), "f"(lo)); return r;
}
__device__ __forceinline__ u32 bf16x2_residual(u32 hi_packed, float p0, float p1) {
    float f0 = __uint_as_float(hi_packed << 16);
    float f1 = __uint_as_float(hi_packed & 0xFFFF0000u);
    return bf16x2_pack(p1 - f1, p0 - f0);
}

// ---------------- prep: elementwise fp32 -> (hi, lo) bf16 ----------------
struct alignas(8) B4 { __nv_bfloat16 v[4]; };

__global__ void split_kernel(const float* __restrict__ in, __nv_bfloat16* __restrict__ hi,
                             __nv_bfloat16* __restrict__ lo, int n4)
{
    int i = blockIdx.x * blockDim.x + threadIdx.x;
    if (i >= n4) return;
    float4 v = ((const float4*)in)[i];
    B4 hb, lb;
    float f[4] = { v.x, v.y, v.z, v.w };
#pragma unroll
    for (int j = 0; j < 4; j++) {
        __nv_bfloat16 h = __float2bfloat16(f[j]);
        hb.v[j] = h;
        lb.v[j] = __float2bfloat16(f[j] - __bfloat162float(h));
    }
    ((B4*)hi)[i] = hb;
    ((B4*)lo)[i] = lb;
}

// ---------------- prep: transpose + split, fp32 [K,N] -> bf16 [N,K] hi/lo ----------------
__global__ void tsplit_kernel(const float* __restrict__ in, __nv_bfloat16* __restrict__ hi,
                              __nv_bfloat16* __restrict__ lo, int K, int N)
{
    __shared__ float t[32][33];
    int n0 = blockIdx.x * 32, k0 = blockIdx.y * 32;
    int tx = threadIdx.x, ty = threadIdx.y;      // 32 x 8
#pragma unroll
    for (int j = 0; j < 4; j++)
        t[ty + 8 * j][tx] = in[(size_t)(k0 + ty + 8 * j) * N + n0 + tx];
    __syncthreads();
#pragma unroll
    for (int j = 0; j < 4; j++) {
        int r = ty + 8 * j;
        float v = t[tx][r];
        __nv_bfloat16 h = __float2bfloat16(v);
        size_t o = (size_t)(n0 + r) * K + k0 + tx;
        hi[o] = h;
        lo[o] = __float2bfloat16(v - __bfloat162float(h));
    }
}

// ---------------- shared GEMM mainloop: split-bf16 via mma.sync ----------------
#define GROW_B   80
#define GTILE_B  (128 * GROW_B)
#define GSTAGE_B (4 * GTILE_B)
#define GEMM_SMEM (2 * GSTAGE_B)

__device__ __forceinline__ void gemm_mainloop(
    const __nv_bfloat16* __restrict__ Ahi, const __nv_bfloat16* __restrict__ Alo,
    const __nv_bfloat16* __restrict__ Bhi, const __nv_bfloat16* __restrict__ Blo,
    char* sm, int K, int row0, int col0, float (&acc)[4][4][4])
{
    const u32 sbase = smem_u32(sm);
    const int tid = threadIdx.x;
    const int wid = tid >> 5, lane = tid & 31;
    const int wm = wid >> 2;
    const int wn = wid & 3;

    const int ku4 = K >> 3;
    const uint4* srcs[4] = {
        (const uint4*)Ahi + (size_t)row0 * ku4,
        (const uint4*)Alo + (size_t)row0 * ku4,
        (const uint4*)Bhi + (size_t)col0 * ku4,
        (const uint4*)Blo + (size_t)col0 * ku4 };

    const int lr0 = tid >> 2;
    const int lc = tid & 3;

    auto load_chunk = [&](int c, int s) {
        const u32 stb = sbase + s * GSTAGE_B;
#pragma unroll
        for (int t = 0; t < 4; t++) {
            const uint4* gp = srcs[t] + (size_t)c * 4 + lc;
#pragma unroll
            for (int j = 0; j < 2; j++) {
                int r = lr0 + j * 64;
                cp_async16(stb + t * GTILE_B + r * GROW_B + lc * 16,
                           gp + (size_t)r * ku4);
            }
        }
        cp_commit();
    };

#pragma unroll
    for (int i = 0; i < 4; i++)
#pragma unroll
        for (int j = 0; j < 4; j++)
#pragma unroll
            for (int e = 0; e < 4; e++) acc[i][j][e] = 0.f;

    load_chunk(0, 0);
    cp_wait0();
    __syncthreads();

    const int NC = K >> 5;
    for (int c = 0; c < NC; c++) {
        const int s = c & 1;
        if (c + 1 < NC) load_chunk(c + 1, s ^ 1);

        const u32 abase = sbase + s * GSTAGE_B;
        const u32 bbase = abase + 2 * GTILE_B;
#pragma unroll
        for (int ks = 0; ks < 2; ks++) {
            u32 ahi[4][4], alo[4][4];
            const u32 acol2 = (ks * 16 + ((lane >> 4) << 3)) * 2;
#pragma unroll
            for (int mt = 0; mt < 4; mt++) {
                u32 ad = abase + (u32)((wm * 64 + mt * 16 + (lane & 15)) * GROW_B) + acol2;
                ldmx4(ahi[mt][0], ahi[mt][1], ahi[mt][2], ahi[mt][3], ad);
                ldmx4(alo[mt][0], alo[mt][1], alo[mt][2], alo[mt][3], ad + GTILE_B);
            }
            const u32 bcol2 = (ks * 16 + (((lane >> 3) & 1) << 3)) * 2;
#pragma unroll
            for (int nt = 0; nt < 4; nt++) {
                u32 bh[2], bl[2];
                u32 bd = bbase + (u32)((wn * 32 + nt * 8 + (lane & 7)) * GROW_B) + bcol2;
                ldmx2(bh[0], bh[1], bd);
                ldmx2(bl[0], bl[1], bd + GTILE_B);
                // term-major: same-accumulator reuse distance = 4
#pragma unroll
                for (int mt = 0; mt < 4; mt++) mma16816(acc[mt][nt], ahi[mt], bh);
#pragma unroll
                for (int mt = 0; mt < 4; mt++) mma16816(acc[mt][nt], ahi[mt], bl);
#pragma unroll
                for (int mt = 0; mt < 4; mt++) mma16816(acc[mt][nt], alo[mt], bh);
            }
        }
        cp_wait0();
        __syncthreads();
    }
}

// ---------------- GEMM, fp32 + bias epilogue (O-proj) ----------------
__global__ __launch_bounds__(256, 2)
void gemm_mma(const __nv_bfloat16* __restrict__ Ahi, const __nv_bfloat16* __restrict__ Alo,
              const __nv_bfloat16* __restrict__ Bhi, const __nv_bfloat16* __restrict__ Blo,
              const float* __restrict__ bias, float* __restrict__ C,
              int M, int N, int K)
{
    extern __shared__ __align__(16) char sm[];
    const int tid = threadIdx.x;
    const int wid = tid >> 5, lane = tid & 31;
    const int wm = wid >> 2, wn = wid & 3;
    const int row0 = blockIdx.y * 128, col0 = blockIdx.x * 128;

    float acc[4][4][4];
    gemm_mainloop(Ahi, Alo, Bhi, Blo, sm, K, row0, col0, acc);

    const int lr = lane >> 2;
    const int ln = (lane & 3) * 2;
#pragma unroll
    for (int mt = 0; mt < 4; mt++) {
#pragma unroll
        for (int nt = 0; nt < 4; nt++) {
            int col = col0 + wn * 32 + nt * 8 + ln;
            float2 bv = *(const float2*)(bias + col);
            int r0 = row0 + wm * 64 + mt * 16 + lr;
            float2 v0 = { acc[mt][nt][0] + bv.x, acc[mt][nt][1] + bv.y };
            float2 v1 = { acc[mt][nt][2] + bv.x, acc[mt][nt][3] + bv.y };
            *(float2*)(C + (size_t)r0 * N + col) = v0;
            *(float2*)(C + (size_t)(r0 + 8) * N + col) = v1;
        }
    }
}

// ---------------- fused Q-proj + KV-proj (wave-packed single launch) ----------------
// blocks [0, 1008): Q tiles (12 x 84);  [1008, 1200): KV tiles (24 x 8)
#define QB_CTAS 1008

__global__ __launch_bounds__(256, 2)
void gemm_qkv(const __nv_bfloat16* __restrict__ xhi, const __nv_bfloat16* __restrict__ xlo,
              const __nv_bfloat16* __restrict__ cxhi, const __nv_bfloat16* __restrict__ cxlo,
              const __nv_bfloat16* __restrict__ wqh, const __nv_bfloat16* __restrict__ wql,
              const __nv_bfloat16* __restrict__ wkh, const __nv_bfloat16* __restrict__ wkl,
              const float* __restrict__ bq, const float* __restrict__ bkv,
              const float* __restrict__ gscale,
              __nv_bfloat16* __restrict__ qhi, __nv_bfloat16* __restrict__ qlo,
              __nv_bfloat16* __restrict__ kvhi, __nv_bfloat16* __restrict__ kvlo)
{
    extern __shared__ __align__(16) char sm[];
    const int tid = threadIdx.x;
    const int wid = tid >> 5, lane = tid & 31;
    const int wm = wid >> 2, wn = wid & 3;

    const int bid = blockIdx.x;
    const bool isQ = bid < QB_CTAS;
    int row0, col0, N;
    const __nv_bfloat16 *Ah, *Al, *Bh, *Bl;
    if (isQ) {
        row0 = (bid / 12) * 128; col0 = (bid % 12) * 128; N = D_;
        Ah = xhi; Al = xlo; Bh = wqh; Bl = wql;
    } else {
        int k2 = bid - QB_CTAS;
        row0 = (k2 / 24) * 128; col0 = (k2 % 24) * 128; N = 2 * D_;
        Ah = cxhi; Al = cxlo; Bh = wkh; Bl = wkl;
    }

    float acc[4][4][4];
    gemm_mainloop(Ah, Al, Bh, Bl, sm, D_, row0, col0, acc);

    const int lr = lane >> 2;
    const int ln = (lane & 3) * 2;

    if (!isQ) {
        // KV epilogue: bias + hi/lo split
#pragma unroll
        for (int mt = 0; mt < 4; mt++) {
#pragma unroll
            for (int nt = 0; nt < 4; nt++) {
                int col = col0 + wn * 32 + nt * 8 + ln;
                float2 bv = *(const float2*)(bkv + col);
                int r0 = row0 + wm * 64 + mt * 16 + lr;
                float v0 = acc[mt][nt][0] + bv.x, v1 = acc[mt][nt][1] + bv.y;
                float v2 = acc[mt][nt][2] + bv.x, v3 = acc[mt][nt][3] + bv.y;
                u32 hp = bf16x2_pack(v1, v0);
                u32 lp = bf16x2_residual(hp, v0, v1);
                *(u32*)(kvhi + (size_t)r0 * N + col) = hp;
                *(u32*)(kvlo + (size_t)r0 * N + col) = lp;
                hp = bf16x2_pack(v3, v2);
                lp = bf16x2_residual(hp, v2, v3);
                *(u32*)(kvhi + (size_t)(r0 + 8) * N + col) = hp;
                *(u32*)(kvlo + (size_t)(r0 + 8) * N + col) = lp;
            }
        }
        return;
    }

    // Q epilogue: bias + RMSNorm(+1/sqrt(HD)) + gscale + hi/lo split
    float ss[4][2];
#pragma unroll
    for (int mt = 0; mt < 4; mt++) { ss[mt][0] = 0.f; ss[mt][1] = 0.f; }
#pragma unroll
    for (int nt = 0; nt < 4; nt++) {
        int col = col0 + wn * 32 + nt * 8 + ln;
        float2 bv = *(const float2*)(bq + col);
#pragma unroll
        for (int mt = 0; mt < 4; mt++) {
            acc[mt][nt][0] += bv.x; acc[mt][nt][1] += bv.y;
            acc[mt][nt][2] += bv.x; acc[mt][nt][3] += bv.y;
            ss[mt][0] += acc[mt][nt][0] * acc[mt][nt][0] + acc[mt][nt][1] * acc[mt][nt][1];
            ss[mt][1] += acc[mt][nt][2] * acc[mt][nt][2] + acc[mt][nt][3] * acc[mt][nt][3];
        }
    }
#pragma unroll
    for (int mt = 0; mt < 4; mt++) {
#pragma unroll
        for (int half = 0; half < 2; half++) {
            ss[mt][half] += __shfl_xor_sync(0xffffffffu, ss[mt][half], 1);
            ss[mt][half] += __shfl_xor_sync(0xffffffffu, ss[mt][half], 2);
        }
    }
    float* ssum = (float*)sm;
    if ((lane & 3) == 0) {
#pragma unroll
        for (int mt = 0; mt < 4; mt++) {
            int lrow = wm * 64 + mt * 16 + lr;
            ssum[wn * 128 + lrow] = ss[mt][0];
            ssum[wn * 128 + lrow + 8] = ss[mt][1];
        }
    }
    __syncthreads();

    const float QK_SCALE = 0.08838834764831845f;
#pragma unroll
    for (int mt = 0; mt < 4; mt++) {
        int lrow = wm * 64 + mt * 16 + lr;
        float s0 = ssum[lrow] + ssum[128 + lrow] + ssum[256 + lrow] + ssum[384 + lrow];
        float s1 = ssum[lrow + 8] + ssum[128 + lrow + 8] + ssum[256 + lrow + 8] + ssum[384 + lrow + 8];
        float r0 = rsqrtf(s0 * (1.0f / 128.0f) + 1e-6f) * QK_SCALE;
        float r1 = rsqrtf(s1 * (1.0f / 128.0f) + 1e-6f) * QK_SCALE;
        int grow = row0 + lrow;
#pragma unroll
        for (int nt = 0; nt < 4; nt++) {
            int hdidx = wn * 32 + nt * 8 + ln;
            float2 gs = *(const float2*)(gscale + hdidx);
            int col = col0 + hdidx;
            float v0 = acc[mt][nt][0] * r0 * gs.x, v1 = acc[mt][nt][1] * r0 * gs.y;
            float v2 = acc[mt][nt][2] * r1 * gs.x, v3 = acc[mt][nt][3] * r1 * gs.y;
            u32 hp = bf16x2_pack(v1, v0);
            u32 lp = bf16x2_residual(hp, v0, v1);
            *(u32*)(qhi + (size_t)grow * N + col) = hp;
            *(u32*)(qlo + (size_t)grow * N + col) = lp;
            hp = bf16x2_pack(v3, v2);
            lp = bf16x2_residual(hp, v2, v3);
            *(u32*)(qhi + (size_t)(grow + 8) * N + col) = hp;
            *(u32*)(qlo + (size_t)(grow + 8) * N + col) = lp;
        }
    }
}

// ---------------- Flash attention via mma.sync, split-bf16, Q-frags in registers ----------------
#define SROW_B 272
#define AQ_TILE (128 * SROW_B)            // 34816 (staging only)
#define AKV_TILE (64 * SROW_B)            // 17408
#define AKV_STAGE (4 * AKV_TILE)          // 69632
#define ATT_SMEM (2 * AKV_STAGE)          // 139264 (Q staged in same region first)

__global__ __launch_bounds__(256, 1)
void attn_mma(const __nv_bfloat16* __restrict__ qhi, const __nv_bfloat16* __restrict__ qlo,
              const __nv_bfloat16* __restrict__ kvhi, const __nv_bfloat16* __restrict__ kvlo,
              __nv_bfloat16* __restrict__ chi, __nv_bfloat16* __restrict__ clo)
{
    extern __shared__ __align__(16) char sm[];
    const u32 sb = smem_u32(sm);
    const int tid = threadIdx.x, wid = tid >> 5, lane = tid & 31;
    const int q0 = blockIdx.x * 128, h = blockIdx.y, b = blockIdx.z;

    // ---- stage Q hi/lo into smem (region later reused by KV stages) ----
    {
        const __nv_bfloat16* s0 = qhi + (size_t)(b * N_Q + q0) * D_ + h * HD_;
        const __nv_bfloat16* s1 = qlo + (size_t)(b * N_Q + q0) * D_ + h * HD_;
#pragma unroll
        for (int j = 0; j < 8; j++) {
            int idx = tid + j * 256;
            int r = idx >> 4, c = idx & 15;
            cp_async16(sb + r * SROW_B + c * 16, s0 + (size_t)r * D_ + c * 8);
            cp_async16(sb + AQ_TILE + r * SROW_B + c * 16, s1 + (size_t)r * D_ + c * 8);
        }
        cp_commit();
        cp_wait0();
        __syncthreads();
    }

    // ---- preload Q fragments to registers (chunk-invariant) ----
    u32 qh[8][4], ql[8][4];
#pragma unroll
    for (int ks = 0; ks < 8; ks++) {
        u32 ar = sb + (u32)((wid * 16 + (lane & 15)) * SROW_B + (ks * 16 + (lane >> 4) * 8) * 2);
        ldmx4(qh[ks][0], qh[ks][1], qh[ks][2], qh[ks][3], ar);
        ldmx4(ql[ks][0], ql[ks][1], ql[ks][2], ql[ks][3], ar + AQ_TILE);
    }
    __syncthreads();   // all warps done reading Q smem before KV overwrites it

    const size_t kvrow0 = (size_t)(b * M_KV) * (2 * D_) + h * HD_;
    auto load_kv = [&](int c, int s) {
        const __nv_bfloat16* arr[4] = {
            kvhi + kvrow0 + (size_t)(c * 64) * (2 * D_),
            kvlo + kvrow0 + (size_t)(c * 64) * (2 * D_),
            kvhi + kvrow0 + (size_t)(c * 64) * (2 * D_) + D_,
            kvlo + kvrow0 + (size_t)(c * 64) * (2 * D_) + D_ };
        const u32 stb = sb + s * AKV_STAGE;
#pragma unroll
        for (int t = 0; t < 4; t++) {
#pragma unroll
            for (int j = 0; j < 4; j++) {
                int idx = tid + j * 256;
                int r = idx >> 4, c16 = idx & 15;
                cp_async16(stb + t * AKV_TILE + r * SROW_B + c16 * 16,
                           arr[t] + (size_t)r * (2 * D_) + c16 * 8);
            }
        }
    };

    load_kv(0, 0);
    cp_commit();
    cp_wait0();
    __syncthreads();

    float o[16][4];
#pragma unroll
    for (int nt = 0; nt < 16; nt++)
#pragma unroll
        for (int e = 0; e < 4; e++) o[nt][e] = 0.f;
    float m0 = -INFINITY, m1 = -INFINITY, l0 = 0.f, l1 = 0.f;

    for (int c = 0; c < 8; c++) {
        const int s = c & 1;
        if (c + 1 < 8) { load_kv(c + 1, s ^ 1); cp_commit(); }

        const u32 kb = sb + s * AKV_STAGE;

        // ---- S = Q @ K^T (3-term split, Q from registers) ----
        float sf[8][4];
#pragma unroll
        for (int t = 0; t < 8; t++)
#pragma unroll
            for (int e = 0; e < 4; e++) sf[t][e] = 0.f;

#pragma unroll
        for (int ks = 0; ks < 8; ks++) {
#pragma unroll
            for (int np = 0; np < 4; np++) {
                u32 ba = kb + (u32)((np * 16 + (lane & 7) + ((lane >> 4) & 1) * 8) * SROW_B
                                    + (ks * 16 + ((lane >> 3) & 1) * 8) * 2);
                u32 b0, b1, b2, b3, c0, c1, c2, c3;
                ldmx4(b0, b1, b2, b3, ba);               // Khi
                ldmx4(c0, c1, c2, c3, ba + AKV_TILE);    // Klo
                u32 bb01[2] = { b0, b1 }, bb23[2] = { b2, b3 };
                u32 cc01[2] = { c0, c1 }, cc23[2] = { c2, c3 };
                mma16816(sf[2 * np],     qh[ks], bb01);
                mma16816(sf[2 * np + 1], qh[ks], bb23);
                mma16816(sf[2 * np],     ql[ks], bb01);
                mma16816(sf[2 * np + 1], ql[ks], bb23);
                mma16816(sf[2 * np],     qh[ks], cc01);
                mma16816(sf[2 * np + 1], qh[ks], cc23);
            }
        }

        // ---- online softmax ----
        float tm0 = -INFINITY, tm1 = -INFINITY;
#pragma unroll
        for (int t = 0; t < 8; t++) {
            tm0 = fmaxf(tm0, fmaxf(sf[t][0], sf[t][1]));
            tm1 = fmaxf(tm1, fmaxf(sf[t][2], sf[t][3]));
        }
        tm0 = fmaxf(tm0, __shfl_xor_sync(0xffffffffu, tm0, 1));
        tm0 = fmaxf(tm0, __shfl_xor_sync(0xffffffffu, tm0, 2));
        tm1 = fmaxf(tm1, __shfl_xor_sync(0xffffffffu, tm1, 1));
        tm1 = fmaxf(tm1, __shfl_xor_sync(0xffffffffu, tm1, 2));
        float mn0 = fmaxf(m0, tm0), mn1 = fmaxf(m1, tm1);
        float cr0 = __expf(m0 - mn0), cr1 = __expf(m1 - mn1);
        m0 = mn0; m1 = mn1;
        float ls0 = 0.f, ls1 = 0.f;
#pragma unroll
        for (int t = 0; t < 8; t++) {
            sf[t][0] = __expf(sf[t][0] - mn0);
            sf[t][1] = __expf(sf[t][1] - mn0);
            sf[t][2] = __expf(sf[t][2] - mn1);
            sf[t][3] = __expf(sf[t][3] - mn1);
            ls0 += sf[t][0] + sf[t][1];
            ls1 += sf[t][2] + sf[t][3];
        }
        ls0 += __shfl_xor_sync(0xffffffffu, ls0, 1);
        ls0 += __shfl_xor_sync(0xffffffffu, ls0, 2);
        ls1 += __shfl_xor_sync(0xffffffffu, ls1, 1);
        ls1 += __shfl_xor_sync(0xffffffffu, ls1, 2);
        l0 = l0 * cr0 + ls0;
        l1 = l1 * cr1 + ls1;
#pragma unroll
        for (int nt = 0; nt < 16; nt++) {
            o[nt][0] *= cr0; o[nt][1] *= cr0;
            o[nt][2] *= cr1; o[nt][3] *= cr1;
        }

        // ---- P -> bf16 hi/lo A-fragments (register-to-register) ----
        u32 phi[4][4], plo[4][4];
#pragma unroll
        for (int kt = 0; kt < 4; kt++) {
            float p00 = sf[2 * kt][0], p01 = sf[2 * kt][1];
            float p10 = sf[2 * kt][2], p11 = sf[2 * kt][3];
            float p20 = sf[2 * kt + 1][0], p21 = sf[2 * kt + 1][1];
            float p30 = sf[2 * kt + 1][2], p31 = sf[2 * kt + 1][3];
            phi[kt][0] = bf16x2_pack(p01, p00); plo[kt][0] = bf16x2_residual(phi[kt][0], p00, p01);
            phi[kt][1] = bf16x2_pack(p11, p10); plo[kt][1] = bf16x2_residual(phi[kt][1], p10, p11);
            phi[kt][2] = bf16x2_pack(p21, p20); plo[kt][2] = bf16x2_residual(phi[kt][2], p20, p21);
            phi[kt][3] = bf16x2_pack(p31, p30); plo[kt][3] = bf16x2_residual(phi[kt][3], p30, p31);
        }

        // ---- O += P @ V (3-term split); V via ldmatrix.trans ----
        const u32 vb = kb + 2 * AKV_TILE;
#pragma unroll
        for (int np = 0; np < 8; np++) {
#pragma unroll
            for (int kt = 0; kt < 4; kt++) {
                u32 va = vb + (u32)((kt * 16 + (lane & 15)) * SROW_B + (np * 16 + (lane >> 4) * 8) * 2);
                u32 b0, b1, b2, b3, c0, c1, c2, c3;
                ldmx4t(b0, b1, b2, b3, va);               // Vhi
                ldmx4t(c0, c1, c2, c3, va + AKV_TILE);    // Vlo
                u32 bb01[2] = { b0, b1 }, bb23[2] = { b2, b3 };
                u32 cc01[2] = { c0, c1 }, cc23[2] = { c2, c3 };
                mma16816(o[2 * np],     phi[kt], bb01);
                mma16816(o[2 * np + 1], phi[kt], bb23);
                mma16816(o[2 * np],     plo[kt], bb01);
                mma16816(o[2 * np + 1], plo[kt], bb23);
                mma16816(o[2 * np],     phi[kt], cc01);
                mma16816(o[2 * np + 1], phi[kt], cc23);
            }
        }

        cp_wait0();
        __syncthreads();
    }

    // ---- normalize + split + write ctx ----
    float inv0 = 1.0f / l0, inv1 = 1.0f / l1;
    int grow = b * N_Q + q0 + wid * 16 + (lane >> 2);
    int gcol = h * HD_ + 2 * (lane & 3);
#pragma unroll
    for (int nt = 0; nt < 16; nt++) {
        int col = gcol + nt * 8;
        size_t off0 = (size_t)grow * D_ + col;
        size_t off8 = (size_t)(grow + 8) * D_ + col;
        float p0 = o[nt][0] * inv0, p1 = o[nt][1] * inv0;
        u32 hp = bf16x2_pack(p1, p0);
        u32 lp = bf16x2_residual(hp, p0, p1);
        *(u32*)(chi + off0) = hp;
        *(u32*)(clo + off0) = lp;
        p0 = o[nt][2] * inv1; p1 = o[nt][3] * inv1;
        hp = bf16x2_pack(p1, p0);
        lp = bf16x2_residual(hp, p0, p1);
        *(u32*)(chi + off8) = hp;
        *(u32*)(clo + off8) = lp;
    }
}

// ---------------- launch ----------------
extern "C" void kernel_launch(void* const* d_in, const int* in_sizes, int n_in,
                              void* d_out, int out_size)
{
    const float* x       = (const float*)d_in[0];
    const float* context = (const float*)d_in[1];
    const float* wq      = (const float*)d_in[2];
    const float* bq      = (const float*)d_in[3];
    const float* wkv     = (const float*)d_in[4];
    const float* bkv     = (const float*)d_in[5];
    const float* wo      = (const float*)d_in[6];
    const float* bo      = (const float*)d_in[7];
    const float* qns     = (const float*)d_in[8];
    float* out = (float*)d_out;

    __nv_bfloat16 *ahi, *alo, *cxhi, *cxlo, *qhi, *qlo, *kvhi, *kvlo;
    __nv_bfloat16 *wqhi, *wqlo, *wkvhi, *wkvlo, *wohi, *wolo;
    cudaGetSymbolAddress((void**)&ahi,   g_ahi);
    cudaGetSymbolAddress((void**)&alo,   g_alo);
    cudaGetSymbolAddress((void**)&cxhi,  g_chi);
    cudaGetSymbolAddress((void**)&cxlo,  g_clo);
    cudaGetSymbolAddress((void**)&qhi,   g_qhi);
    cudaGetSymbolAddress((void**)&qlo,   g_qlo);
    cudaGetSymbolAddress((void**)&kvhi,  g_kvhi);
    cudaGetSymbolAddress((void**)&kvlo,  g_kvlo);
    cudaGetSymbolAddress((void**)&wqhi,  g_wqhi);
    cudaGetSymbolAddress((void**)&wqlo,  g_wqlo);
    cudaGetSymbolAddress((void**)&wkvhi, g_wkvhi);
    cudaGetSymbolAddress((void**)&wkvlo, g_wkvlo);
    cudaGetSymbolAddress((void**)&wohi,  g_wohi);
    cudaGetSymbolAddress((void**)&wolo,  g_wolo);

    cudaFuncSetAttribute(gemm_mma, cudaFuncAttributeMaxDynamicSharedMemorySize, GEMM_SMEM);
    cudaFuncSetAttribute(gemm_qkv, cudaFuncAttributeMaxDynamicSharedMemorySize, GEMM_SMEM);
    cudaFuncSetAttribute(attn_mma, cudaFuncAttributeMaxDynamicSharedMemorySize, ATT_SMEM);

    // weight transpose+split
    tsplit_kernel<<<dim3(D_ / 32, D_ / 32), dim3(32, 8)>>>(wq, wqhi, wqlo, D_, D_);
    tsplit_kernel<<<dim3((2 * D_) / 32, D_ / 32), dim3(32, 8)>>>(wkv, wkvhi, wkvlo, D_, 2 * D_);
    tsplit_kernel<<<dim3(D_ / 32, D_ / 32), dim3(32, 8)>>>(wo, wohi, wolo, D_, D_);

    // activation splits
    {
        int n4 = (B_ * N_Q * D_) / 4;
        split_kernel<<<(n4 + 255) / 256, 256>>>(x, ahi, alo, n4);
        int c4 = (B_ * M_KV * D_) / 4;
        split_kernel<<<(c4 + 255) / 256, 256>>>(context, cxhi, cxlo, c4);
    }

    // fused Q-proj (+rmsnorm+scale+split) and KV-proj (+split), one wave-packed launch
    gemm_qkv<<<QB_CTAS + 192, 256, GEMM_SMEM>>>(
        ahi, alo, cxhi, cxlo, wqhi, wqlo, wkvhi, wkvlo,
        bq, bkv, qns, qhi, qlo, kvhi, kvlo);

    // attention -> ctx hi/lo directly into ahi/alo
    attn_mma<<<dim3(N_Q / 128, H_, B_), 256, ATT_SMEM>>>(qhi, qlo, kvhi, kvlo, ahi, alo);

    // out = ctx @ wo + bo
    gemm_mma<<<dim3(D_ / 128, (B_ * N_Q) / 128), 256, GEMM_SMEM>>>(
        ahi, alo, wohi, wolo, bo, out, B_ * N_Q, D_, D_);
}

// round 11
// speedup vs baseline: 5.9921x; 2.1930x over previous
#include <cuda_runtime.h>
#include <cuda_fp16.h>
#include <stdint.h>
#include <math.h>

// Problem dims (fixed)
#define B_   2
#define N_Q  5376
#define M_KV 512
#define D_   1536
#define H_   12
#define HD_  128

// ---------------- scratch (device globals: allocation-guard safe) ----------------
__device__ __half g_a[(size_t)B_ * N_Q * D_];          // x (then reused for ctx)
__device__ __half g_cx[(size_t)B_ * M_KV * D_];        // context
__device__ __half g_q[(size_t)B_ * N_Q * D_];
__device__ __half g_kv[(size_t)B_ * M_KV * 2 * D_];
__device__ __half g_wq[(size_t)D_ * D_];
__device__ __half g_wkv[(size_t)2 * D_ * D_];
__device__ __half g_wo[(size_t)D_ * D_];

// ---------------- helpers ----------------
typedef unsigned long long u64;
typedef unsigned int u32;

__device__ __forceinline__ u32 smem_u32(const void* p) {
    u32 a;
    asm("{ .reg .u64 t; cvta.to.shared.u64 t, %1; cvt.u32.u64 %0, t; }" : "=r"(a) : "l"(p));
    return a;
}
__device__ __forceinline__ void cp_async16(u32 dst, const void* src) {
    asm volatile("cp.async.cg.shared.global [%0], [%1], 16;" :: "r"(dst), "l"(src) : "memory");
}
__device__ __forceinline__ void cp_commit() {
    asm volatile("cp.async.commit_group;" ::: "memory");
}
__device__ __forceinline__ void cp_wait0() {
    asm volatile("cp.async.wait_group 0;" ::: "memory");
}
__device__ __forceinline__ void ldmx4(u32& r0, u32& r1, u32& r2, u32& r3, u32 addr) {
    asm volatile("ldmatrix.sync.aligned.m8n8.x4.shared.b16 {%0,%1,%2,%3}, [%4];"
                 : "=r"(r0), "=r"(r1), "=r"(r2), "=r"(r3) : "r"(addr));
}
__device__ __forceinline__ void ldmx4t(u32& r0, u32& r1, u32& r2, u32& r3, u32 addr) {
    asm volatile("ldmatrix.sync.aligned.m8n8.x4.trans.shared.b16 {%0,%1,%2,%3}, [%4];"
                 : "=r"(r0), "=r"(r1), "=r"(r2), "=r"(r3) : "r"(addr));
}
__device__ __forceinline__ void mma16816(float* c, const u32* a, const u32* b) {
    asm volatile(
        "mma.sync.aligned.m16n8k16.row.col.f32.f16.f16.f32 "
        "{%0,%1,%2,%3}, {%4,%5,%6,%7}, {%8,%9}, {%0,%1,%2,%3};"
        : "+f"(c[0]), "+f"(c[1]), "+f"(c[2]), "+f"(c[3])
        : "r"(a[0]), "r"(a[1]), "r"(a[2]), "r"(a[3]), "r"(b[0]), "r"(b[1]));
}
__device__ __forceinline__ u32 f16x2_pack(float hi, float lo) {
    u32 r; asm("cvt.rn.f16x2.f32 %0, %1, %2;" : "=r"(r) : "f"(hi), "f"(lo)); return r;
}

// ---------------- prep: elementwise fp32 -> fp16 ----------------
struct alignas(8) H4 { __half v[4]; };

__global__ void cvt_kernel(const float* __restrict__ in, __half* __restrict__ out, int n4)
{
    int i = blockIdx.x * blockDim.x + threadIdx.x;
    if (i >= n4) return;
    float4 v = ((const float4*)in)[i];
    H4 h;
    h.v[0] = __float2half_rn(v.x);
    h.v[1] = __float2half_rn(v.y);
    h.v[2] = __float2half_rn(v.z);
    h.v[3] = __float2half_rn(v.w);
    ((H4*)out)[i] = h;
}

// ---------------- prep: transpose + cvt, fp32 [K,N] -> fp16 [N,K] ----------------
__global__ void tcvt_kernel(const float* __restrict__ in, __half* __restrict__ out, int K, int N)
{
    __shared__ float t[32][33];
    int n0 = blockIdx.x * 32, k0 = blockIdx.y * 32;
    int tx = threadIdx.x, ty = threadIdx.y;      // 32 x 8
#pragma unroll
    for (int j = 0; j < 4; j++)
        t[ty + 8 * j][tx] = in[(size_t)(k0 + ty + 8 * j) * N + n0 + tx];
    __syncthreads();
#pragma unroll
    for (int j = 0; j < 4; j++) {
        int r = ty + 8 * j;
        out[(size_t)(n0 + r) * K + k0 + tx] = __float2half_rn(t[tx][r]);
    }
}

// ---------------- shared GEMM mainloop: fp16 via mma.sync ----------------
// C_tile[128,128] = A[M,K] @ B^T (B stored [N,K] K-major).
#define GROW_B   80
#define GTILE_B  (128 * GROW_B)             // 10240
#define GSTAGE_B (2 * GTILE_B)              // 20480 (A | B)
#define GEMM_SMEM (2 * GSTAGE_B)            // 40960

__device__ __forceinline__ void gemm_mainloop(
    const __half* __restrict__ A, const __half* __restrict__ B,
    char* sm, int K, int row0, int col0, float (&acc)[4][4][4])
{
    const u32 sbase = smem_u32(sm);
    const int tid = threadIdx.x;
    const int wid = tid >> 5, lane = tid & 31;
    const int wm = wid >> 2;
    const int wn = wid & 3;

    const int ku4 = K >> 3;
    const uint4* srcs[2] = {
        (const uint4*)A + (size_t)row0 * ku4,
        (const uint4*)B + (size_t)col0 * ku4 };

    const int lr0 = tid >> 2;                // 0..63
    const int lc = tid & 3;                  // 0..3

    auto load_chunk = [&](int c, int s) {
        const u32 stb = sbase + s * GSTAGE_B;
#pragma unroll
        for (int t = 0; t < 2; t++) {
            const uint4* gp = srcs[t] + (size_t)c * 4 + lc;
#pragma unroll
            for (int j = 0; j < 2; j++) {
                int r = lr0 + j * 64;
                cp_async16(stb + t * GTILE_B + r * GROW_B + lc * 16,
                           gp + (size_t)r * ku4);
            }
        }
        cp_commit();
    };

#pragma unroll
    for (int i = 0; i < 4; i++)
#pragma unroll
        for (int j = 0; j < 4; j++)
#pragma unroll
            for (int e = 0; e < 4; e++) acc[i][j][e] = 0.f;

    load_chunk(0, 0);
    cp_wait0();
    __syncthreads();

    const int NC = K >> 5;
    for (int c = 0; c < NC; c++) {
        const int s = c & 1;
        if (c + 1 < NC) load_chunk(c + 1, s ^ 1);

        const u32 abase = sbase + s * GSTAGE_B;
        const u32 bbase = abase + GTILE_B;
#pragma unroll
        for (int ks = 0; ks < 2; ks++) {
            u32 af[4][4];
            const u32 acol2 = (ks * 16 + ((lane >> 4) << 3)) * 2;
#pragma unroll
            for (int mt = 0; mt < 4; mt++) {
                u32 ad = abase + (u32)((wm * 64 + mt * 16 + (lane & 15)) * GROW_B) + acol2;
                ldmx4(af[mt][0], af[mt][1], af[mt][2], af[mt][3], ad);
            }
            const u32 bcol2 = (ks * 16 + ((lane >> 3) & 1) * 8) * 2;
#pragma unroll
            for (int ntp = 0; ntp < 2; ntp++) {
                u32 b0, b1, b2, b3;
                u32 bd = bbase + (u32)((wn * 32 + ntp * 16 + (lane & 7) + ((lane >> 4) & 1) * 8) * GROW_B) + bcol2;
                ldmx4(b0, b1, b2, b3, bd);
                u32 bb01[2] = { b0, b1 }, bb23[2] = { b2, b3 };
#pragma unroll
                for (int mt = 0; mt < 4; mt++) mma16816(acc[mt][2 * ntp], af[mt], bb01);
#pragma unroll
                for (int mt = 0; mt < 4; mt++) mma16816(acc[mt][2 * ntp + 1], af[mt], bb23);
            }
        }
        cp_wait0();
        __syncthreads();
    }
}

// ---------------- GEMM, fp32 + bias epilogue (O-proj) ----------------
__global__ __launch_bounds__(256, 2)
void gemm_mma(const __half* __restrict__ A, const __half* __restrict__ B,
              const float* __restrict__ bias, float* __restrict__ C,
              int M, int N, int K)
{
    extern __shared__ __align__(16) char sm[];
    const int tid = threadIdx.x;
    const int wid = tid >> 5, lane = tid & 31;
    const int wm = wid >> 2, wn = wid & 3;
    const int row0 = blockIdx.y * 128, col0 = blockIdx.x * 128;

    float acc[4][4][4];
    gemm_mainloop(A, B, sm, K, row0, col0, acc);

    const int lr = lane >> 2;
    const int ln = (lane & 3) * 2;
#pragma unroll
    for (int mt = 0; mt < 4; mt++) {
#pragma unroll
        for (int nt = 0; nt < 4; nt++) {
            int col = col0 + wn * 32 + nt * 8 + ln;
            float2 bv = *(const float2*)(bias + col);
            int r0 = row0 + wm * 64 + mt * 16 + lr;
            float2 v0 = { acc[mt][nt][0] + bv.x, acc[mt][nt][1] + bv.y };
            float2 v1 = { acc[mt][nt][2] + bv.x, acc[mt][nt][3] + bv.y };
            *(float2*)(C + (size_t)r0 * N + col) = v0;
            *(float2*)(C + (size_t)(r0 + 8) * N + col) = v1;
        }
    }
}

// ---------------- fused Q-proj + KV-proj (wave-packed single launch) ----------------
// blocks [0, 1008): Q tiles (12 x 84);  [1008, 1200): KV tiles (24 x 8)
#define QB_CTAS 1008

__global__ __launch_bounds__(256, 2)
void gemm_qkv(const __half* __restrict__ x, const __half* __restrict__ cx,
              const __half* __restrict__ wq, const __half* __restrict__ wkv,
              const float* __restrict__ bq, const float* __restrict__ bkv,
              const float* __restrict__ gscale,
              __half* __restrict__ q, __half* __restrict__ kv)
{
    extern __shared__ __align__(16) char sm[];
    const int tid = threadIdx.x;
    const int wid = tid >> 5, lane = tid & 31;
    const int wm = wid >> 2, wn = wid & 3;

    const int bid = blockIdx.x;
    const bool isQ = bid < QB_CTAS;
    int row0, col0, N;
    const __half *A, *B;
    if (isQ) {
        row0 = (bid / 12) * 128; col0 = (bid % 12) * 128; N = D_;
        A = x; B = wq;
    } else {
        int k2 = bid - QB_CTAS;
        row0 = (k2 / 24) * 128; col0 = (k2 % 24) * 128; N = 2 * D_;
        A = cx; B = wkv;
    }

    float acc[4][4][4];
    gemm_mainloop(A, B, sm, D_, row0, col0, acc);

    const int lr = lane >> 2;
    const int ln = (lane & 3) * 2;

    if (!isQ) {
        // KV epilogue: bias + fp16 write
#pragma unroll
        for (int mt = 0; mt < 4; mt++) {
#pragma unroll
            for (int nt = 0; nt < 4; nt++) {
                int col = col0 + wn * 32 + nt * 8 + ln;
                float2 bv = *(const float2*)(bkv + col);
                int r0 = row0 + wm * 64 + mt * 16 + lr;
                float v0 = acc[mt][nt][0] + bv.x, v1 = acc[mt][nt][1] + bv.y;
                float v2 = acc[mt][nt][2] + bv.x, v3 = acc[mt][nt][3] + bv.y;
                *(u32*)(kv + (size_t)r0 * N + col) = f16x2_pack(v1, v0);
                *(u32*)(kv + (size_t)(r0 + 8) * N + col) = f16x2_pack(v3, v2);
            }
        }
        return;
    }

    // Q epilogue: bias + RMSNorm(+1/sqrt(HD)) + gscale + fp16 write
    float ss[4][2];
#pragma unroll
    for (int mt = 0; mt < 4; mt++) { ss[mt][0] = 0.f; ss[mt][1] = 0.f; }
#pragma unroll
    for (int nt = 0; nt < 4; nt++) {
        int col = col0 + wn * 32 + nt * 8 + ln;
        float2 bv = *(const float2*)(bq + col);
#pragma unroll
        for (int mt = 0; mt < 4; mt++) {
            acc[mt][nt][0] += bv.x; acc[mt][nt][1] += bv.y;
            acc[mt][nt][2] += bv.x; acc[mt][nt][3] += bv.y;
            ss[mt][0] += acc[mt][nt][0] * acc[mt][nt][0] + acc[mt][nt][1] * acc[mt][nt][1];
            ss[mt][1] += acc[mt][nt][2] * acc[mt][nt][2] + acc[mt][nt][3] * acc[mt][nt][3];
        }
    }
#pragma unroll
    for (int mt = 0; mt < 4; mt++) {
#pragma unroll
        for (int half = 0; half < 2; half++) {
            ss[mt][half] += __shfl_xor_sync(0xffffffffu, ss[mt][half], 1);
            ss[mt][half] += __shfl_xor_sync(0xffffffffu, ss[mt][half], 2);
        }
    }
    float* ssum = (float*)sm;
    if ((lane & 3) == 0) {
#pragma unroll
        for (int mt = 0; mt < 4; mt++) {
            int lrow = wm * 64 + mt * 16 + lr;
            ssum[wn * 128 + lrow] = ss[mt][0];
            ssum[wn * 128 + lrow + 8] = ss[mt][1];
        }
    }
    __syncthreads();

    const float QK_SCALE = 0.08838834764831845f;
#pragma unroll
    for (int mt = 0; mt < 4; mt++) {
        int lrow = wm * 64 + mt * 16 + lr;
        float s0 = ssum[lrow] + ssum[128 + lrow] + ssum[256 + lrow] + ssum[384 + lrow];
        float s1 = ssum[lrow + 8] + ssum[128 + lrow + 8] + ssum[256 + lrow + 8] + ssum[384 + lrow + 8];
        float r0 = rsqrtf(s0 * (1.0f / 128.0f) + 1e-6f) * QK_SCALE;
        float r1 = rsqrtf(s1 * (1.0f / 128.0f) + 1e-6f) * QK_SCALE;
        int grow = row0 + lrow;
#pragma unroll
        for (int nt = 0; nt < 4; nt++) {
            int hdidx = wn * 32 + nt * 8 + ln;
            float2 gs = *(const float2*)(gscale + hdidx);
            int col = col0 + hdidx;
            float v0 = acc[mt][nt][0] * r0 * gs.x, v1 = acc[mt][nt][1] * r0 * gs.y;
            float v2 = acc[mt][nt][2] * r1 * gs.x, v3 = acc[mt][nt][3] * r1 * gs.y;
            *(u32*)(q + (size_t)grow * N + col) = f16x2_pack(v1, v0);
            *(u32*)(q + (size_t)(grow + 8) * N + col) = f16x2_pack(v3, v2);
        }
    }
}

// ---------------- Flash attention via mma.sync fp16, Q-frags in registers ----------------
#define SROW_B 272
#define AQ_TILE (128 * SROW_B)            // 34816 (staging; reuses stage 0 region)
#define AKV_TILE (64 * SROW_B)            // 17408
#define AKV_STAGE (2 * AKV_TILE)          // 34816: K | V
#define ATT_SMEM (2 * AKV_STAGE)          // 69632

__global__ __launch_bounds__(256, 1)
void attn_mma(const __half* __restrict__ q, const __half* __restrict__ kvp,
              __half* __restrict__ ctx)
{
    extern __shared__ __align__(16) char sm[];
    const u32 sb = smem_u32(sm);
    const int tid = threadIdx.x, wid = tid >> 5, lane = tid & 31;
    const int q0 = blockIdx.x * 128, h = blockIdx.y, b = blockIdx.z;

    // ---- stage Q into smem (stage-0 region), then hoist frags to registers ----
    {
        const __half* s0 = q + (size_t)(b * N_Q + q0) * D_ + h * HD_;
#pragma unroll
        for (int j = 0; j < 8; j++) {
            int idx = tid + j * 256;
            int r = idx >> 4, c = idx & 15;
            cp_async16(sb + r * SROW_B + c * 16, s0 + (size_t)r * D_ + c * 8);
        }
        cp_commit();
        cp_wait0();
        __syncthreads();
    }

    u32 qh[8][4];
#pragma unroll
    for (int ks = 0; ks < 8; ks++) {
        u32 ar = sb + (u32)((wid * 16 + (lane & 15)) * SROW_B + (ks * 16 + (lane >> 4) * 8) * 2);
        ldmx4(qh[ks][0], qh[ks][1], qh[ks][2], qh[ks][3], ar);
    }
    __syncthreads();   // all warps done reading Q smem before KV overwrites it

    const size_t kvrow0 = (size_t)(b * M_KV) * (2 * D_) + h * HD_;
    auto load_kv = [&](int c, int s) {
        const __half* arr[2] = {
            kvp + kvrow0 + (size_t)(c * 64) * (2 * D_),          // K
            kvp + kvrow0 + (size_t)(c * 64) * (2 * D_) + D_ };   // V
        const u32 stb = sb + s * AKV_STAGE;
#pragma unroll
        for (int t = 0; t < 2; t++) {
#pragma unroll
            for (int j = 0; j < 4; j++) {
                int idx = tid + j * 256;
                int r = idx >> 4, c16 = idx & 15;
                cp_async16(stb + t * AKV_TILE + r * SROW_B + c16 * 16,
                           arr[t] + (size_t)r * (2 * D_) + c16 * 8);
            }
        }
    };

    load_kv(0, 0);
    cp_commit();
    cp_wait0();
    __syncthreads();

    float o[16][4];
#pragma unroll
    for (int nt = 0; nt < 16; nt++)
#pragma unroll
        for (int e = 0; e < 4; e++) o[nt][e] = 0.f;
    float m0 = -INFINITY, m1 = -INFINITY, l0 = 0.f, l1 = 0.f;

    for (int c = 0; c < 8; c++) {
        const int s = c & 1;
        if (c + 1 < 8) { load_kv(c + 1, s ^ 1); cp_commit(); }

        const u32 kb = sb + s * AKV_STAGE;

        // ---- S = Q @ K^T ----
        float sf[8][4];
#pragma unroll
        for (int t = 0; t < 8; t++)
#pragma unroll
            for (int e = 0; e < 4; e++) sf[t][e] = 0.f;

#pragma unroll
        for (int ks = 0; ks < 8; ks++) {
#pragma unroll
            for (int np = 0; np < 4; np++) {
                u32 ba = kb + (u32)((np * 16 + (lane & 7) + ((lane >> 4) & 1) * 8) * SROW_B
                                    + (ks * 16 + ((lane >> 3) & 1) * 8) * 2);
                u32 b0, b1, b2, b3;
                ldmx4(b0, b1, b2, b3, ba);
                u32 bb01[2] = { b0, b1 }, bb23[2] = { b2, b3 };
                mma16816(sf[2 * np],     qh[ks], bb01);
                mma16816(sf[2 * np + 1], qh[ks], bb23);
            }
        }

        // ---- online softmax ----
        float tm0 = -INFINITY, tm1 = -INFINITY;
#pragma unroll
        for (int t = 0; t < 8; t++) {
            tm0 = fmaxf(tm0, fmaxf(sf[t][0], sf[t][1]));
            tm1 = fmaxf(tm1, fmaxf(sf[t][2], sf[t][3]));
        }
        tm0 = fmaxf(tm0, __shfl_xor_sync(0xffffffffu, tm0, 1));
        tm0 = fmaxf(tm0, __shfl_xor_sync(0xffffffffu, tm0, 2));
        tm1 = fmaxf(tm1, __shfl_xor_sync(0xffffffffu, tm1, 1));
        tm1 = fmaxf(tm1, __shfl_xor_sync(0xffffffffu, tm1, 2));
        float mn0 = fmaxf(m0, tm0), mn1 = fmaxf(m1, tm1);
        float cr0 = __expf(m0 - mn0), cr1 = __expf(m1 - mn1);
        m0 = mn0; m1 = mn1;
        float ls0 = 0.f, ls1 = 0.f;
#pragma unroll
        for (int t = 0; t < 8; t++) {
            sf[t][0] = __expf(sf[t][0] - mn0);
            sf[t][1] = __expf(sf[t][1] - mn0);
            sf[t][2] = __expf(sf[t][2] - mn1);
            sf[t][3] = __expf(sf[t][3] - mn1);
            ls0 += sf[t][0] + sf[t][1];
            ls1 += sf[t][2] + sf[t][3];
        }
        ls0 += __shfl_xor_sync(0xffffffffu, ls0, 1);
        ls0 += __shfl_xor_sync(0xffffffffu, ls0, 2);
        ls1 += __shfl_xor_sync(0xffffffffu, ls1, 1);
        ls1 += __shfl_xor_sync(0xffffffffu, ls1, 2);
        l0 = l0 * cr0 + ls0;
        l1 = l1 * cr1 + ls1;
#pragma unroll
        for (int nt = 0; nt < 16; nt++) {
            o[nt][0] *= cr0; o[nt][1] *= cr0;
            o[nt][2] *= cr1; o[nt][3] *= cr1;
        }

        // ---- P -> fp16 A-fragments (register-to-register) ----
        u32 pf[4][4];
#pragma unroll
        for (int kt = 0; kt < 4; kt++) {
            pf[kt][0] = f16x2_pack(sf[2 * kt][1],     sf[2 * kt][0]);
            pf[kt][1] = f16x2_pack(sf[2 * kt][3],     sf[2 * kt][2]);
            pf[kt][2] = f16x2_pack(sf[2 * kt + 1][1], sf[2 * kt + 1][0]);
            pf[kt][3] = f16x2_pack(sf[2 * kt + 1][3], sf[2 * kt + 1][2]);
        }

        // ---- O += P @ V; V via ldmatrix.trans ----
        const u32 vb = kb + AKV_TILE;
#pragma unroll
        for (int np = 0; np < 8; np++) {
#pragma unroll
            for (int kt = 0; kt < 4; kt++) {
                u32 va = vb + (u32)((kt * 16 + (lane & 15)) * SROW_B + (np * 16 + (lane >> 4) * 8) * 2);
                u32 b0, b1, b2, b3;
                ldmx4t(b0, b1, b2, b3, va);
                u32 bb01[2] = { b0, b1 }, bb23[2] = { b2, b3 };
                mma16816(o[2 * np],     pf[kt], bb01);
                mma16816(o[2 * np + 1], pf[kt], bb23);
            }
        }

        cp_wait0();
        __syncthreads();
    }

    // ---- normalize + write ctx (fp16) ----
    float inv0 = 1.0f / l0, inv1 = 1.0f / l1;
    int grow = b * N_Q + q0 + wid * 16 + (lane >> 2);
    int gcol = h * HD_ + 2 * (lane & 3);
#pragma unroll
    for (int nt = 0; nt < 16; nt++) {
        int col = gcol + nt * 8;
        *(u32*)(ctx + (size_t)grow * D_ + col) =
            f16x2_pack(o[nt][1] * inv0, o[nt][0] * inv0);
        *(u32*)(ctx + (size_t)(grow + 8) * D_ + col) =
            f16x2_pack(o[nt][3] * inv1, o[nt][2] * inv1);
    }
}

// ---------------- launch ----------------
extern "C" void kernel_launch(void* const* d_in, const int* in_sizes, int n_in,
                              void* d_out, int out_size)
{
    const float* x       = (const float*)d_in[0];
    const float* context = (const float*)d_in[1];
    const float* wq      = (const float*)d_in[2];
    const float* bq      = (const float*)d_in[3];
    const float* wkv     = (const float*)d_in[4];
    const float* bkv     = (const float*)d_in[5];
    const float* wo      = (const float*)d_in[6];
    const float* bo      = (const float*)d_in[7];
    const float* qns     = (const float*)d_in[8];
    float* out = (float*)d_out;

    __half *a, *cx, *q, *kv, *hwq, *hwkv, *hwo;
    cudaGetSymbolAddress((void**)&a,    g_a);
    cudaGetSymbolAddress((void**)&cx,   g_cx);
    cudaGetSymbolAddress((void**)&q,    g_q);
    cudaGetSymbolAddress((void**)&kv,   g_kv);
    cudaGetSymbolAddress((void**)&hwq,  g_wq);
    cudaGetSymbolAddress((void**)&hwkv, g_wkv);
    cudaGetSymbolAddress((void**)&hwo,  g_wo);

    cudaFuncSetAttribute(gemm_mma, cudaFuncAttributeMaxDynamicSharedMemorySize, GEMM_SMEM);
    cudaFuncSetAttribute(gemm_qkv, cudaFuncAttributeMaxDynamicSharedMemorySize, GEMM_SMEM);
    cudaFuncSetAttribute(attn_mma, cudaFuncAttributeMaxDynamicSharedMemorySize, ATT_SMEM);

    // weight transpose+convert: [K,N] fp32 -> [N,K] fp16
    tcvt_kernel<<<dim3(D_ / 32, D_ / 32), dim3(32, 8)>>>(wq, hwq, D_, D_);
    tcvt_kernel<<<dim3((2 * D_) / 32, D_ / 32), dim3(32, 8)>>>(wkv, hwkv, D_, 2 * D_);
    tcvt_kernel<<<dim3(D_ / 32, D_ / 32), dim3(32, 8)>>>(wo, hwo, D_, D_);

    // activation converts
    {
        int n4 = (B_ * N_Q * D_) / 4;
        cvt_kernel<<<(n4 + 255) / 256, 256>>>(x, a, n4);
        int c4 = (B_ * M_KV * D_) / 4;
        cvt_kernel<<<(c4 + 255) / 256, 256>>>(context, cx, c4);
    }

    // fused Q-proj (+rmsnorm+scale) and KV-proj, one wave-packed launch
    gemm_qkv<<<QB_CTAS + 192, 256, GEMM_SMEM>>>(
        a, cx, hwq, hwkv, bq, bkv, qns, q, kv);

    // attention -> ctx fp16 (reuses x buffer)
    attn_mma<<<dim3(N_Q / 128, H_, B_), 256, ATT_SMEM>>>(q, kv, a);

    // out = ctx @ wo + bo
    gemm_mma<<<dim3(D_ / 128, (B_ * N_Q) / 128), 256, GEMM_SMEM>>>(
        a, hwo, bo, out, B_ * N_Q, D_, D_);
}